// round 11
// baseline (speedup 1.0000x reference)
#include <cuda_runtime.h>
#include <cuda_bf16.h>
#include <math.h>
#include <stdint.h>

// ---------------- problem constants ----------------
#define L_TXT 256
#define L_IMG 1024
#define L_TMP 1024
#define L_ALL 2304          // txt + img + tmp
#define D_MODEL 1024
#define NH 16
#define HD 64
#define D_MLP 4096
#define EPS 1e-6f
#define ATTN_SCALE 0.125f   // 1/sqrt(64)

// ---------------- scratch (static device memory; no allocation) ----------------
__device__ float g_mod[3 * 6144];
__device__ float g_res[L_ALL * D_MODEL];       // concat copy of original inputs [txt|img|tmp]
__device__ float g_xm[L_ALL * D_MODEL];        // LN1-modulated, concat order [txt|img|tmp]
__device__ float g_qkv[L_ALL * 3 * D_MODEL];   // QKV gemm out, same row order
__device__ float g_Q[NH * L_ALL * HD];
__device__ float g_K[NH * L_ALL * HD];
__device__ float g_V[NH * L_ALL * HD];
__device__ float g_attn[L_ALL * D_MODEL];      // [l][h*64+d], concat order
__device__ float g_x1[L_ALL * D_MODEL];        // post-proj residual, concat order
__device__ float g_ym[1280 * D_MODEL];         // LN2-modulated (img rows 0..1023, txt rows 1024..1279)
__device__ float g_h[1280 * D_MLP];            // MLP hidden

// ---------------- helpers ----------------
__device__ __forceinline__ float gelu_tanh(float x) {
    const float c = 0.7978845608028654f; // sqrt(2/pi)
    float x3 = x * x * x;
    return 0.5f * x * (1.f + tanhf(c * (x + 0.044715f * x3)));
}

__device__ __forceinline__ uint32_t f2tf32(float f) {
    uint32_t u;
    asm("cvt.rna.tf32.f32 %0, %1;" : "=r"(u) : "f"(f));
    return u;
}

__device__ __forceinline__ void mma_tf32(float& d0, float& d1, float& d2, float& d3,
                                         uint32_t a0, uint32_t a1, uint32_t a2, uint32_t a3,
                                         uint32_t b0, uint32_t b1) {
    asm volatile(
        "mma.sync.aligned.m16n8k8.row.col.f32.tf32.tf32.f32 "
        "{%0,%1,%2,%3}, {%4,%5,%6,%7}, {%8,%9}, {%0,%1,%2,%3};"
        : "+f"(d0), "+f"(d1), "+f"(d2), "+f"(d3)
        : "r"(a0), "r"(a1), "r"(a2), "r"(a3), "r"(b0), "r"(b1));
}

// ---------------- concat copy of residual sources ----------------
__global__ void copy3_kernel(const float* __restrict__ txt, const float* __restrict__ img,
                             const float* __restrict__ tmp, float* __restrict__ dst) {
    int i = blockIdx.x * 256 + threadIdx.x;    // float4 index, total L_ALL*1024/4
    const int ntxt = L_TXT * D_MODEL / 4;
    const int nimg = (L_TXT + L_IMG) * D_MODEL / 4;
    float4 v;
    if (i < ntxt)       v = ((const float4*)txt)[i];
    else if (i < nimg)  v = ((const float4*)img)[i - ntxt];
    else                v = ((const float4*)tmp)[i - nimg];
    ((float4*)dst)[i] = v;
}

// ---------------- mod = silu(vec) @ mod_w + mod_b  (3 x 6144 outputs; silu fused) ----------------
__global__ void mod_kernel(const float* __restrict__ vecp, const float* __restrict__ mod_w,
                           const float* __restrict__ mod_b, float* __restrict__ mod) {
    __shared__ float s_sv[D_MODEL];
    for (int i = threadIdx.x; i < D_MODEL; i += 256) {
        float x = vecp[i];
        s_sv[i] = x / (1.f + expf(-x));
    }
    __syncthreads();
    int o = blockIdx.x * 256 + threadIdx.x;       // 0 .. 3*6144-1
    int i = o / 6144;
    int j = o - i * 6144;
    const float* w = mod_w + (size_t)i * D_MODEL * 6144 + j;
    float acc = 0.f;
    #pragma unroll 8
    for (int d = 0; d < D_MODEL; ++d) acc = fmaf(s_sv[d], w[(size_t)d * 6144], acc);
    mod[o] = acc + mod_b[o];
}

// ---------------- LN + modulate: out = (1+sc)*ln(x) + sh ----------------
__global__ void lnmod_kernel(const float* __restrict__ x, float* __restrict__ out,
                             const float* __restrict__ sh, const float* __restrict__ sc) {
    int r = blockIdx.x;
    const float* xr = x + (size_t)r * D_MODEL;
    int t = threadIdx.x; // 256
    float v[4]; float sum = 0.f, sq = 0.f;
    #pragma unroll
    for (int i = 0; i < 4; i++) { float f = xr[t + i * 256]; v[i] = f; sum += f; sq += f * f; }
    #pragma unroll
    for (int o = 16; o; o >>= 1) {
        sum += __shfl_xor_sync(0xffffffffu, sum, o);
        sq  += __shfl_xor_sync(0xffffffffu, sq, o);
    }
    __shared__ float ssum[8], ssq[8];
    int w = t >> 5, lane = t & 31;
    if (lane == 0) { ssum[w] = sum; ssq[w] = sq; }
    __syncthreads();
    if (t == 0) {
        float S = 0.f, Q = 0.f;
        #pragma unroll
        for (int i = 0; i < 8; i++) { S += ssum[i]; Q += ssq[i]; }
        float mean = S * (1.f / D_MODEL);
        float var  = Q * (1.f / D_MODEL) - mean * mean;
        ssum[0] = mean; ssq[0] = rsqrtf(var + EPS);
    }
    __syncthreads();
    float mean = ssum[0], inv = ssq[0];
    float* orow = out + (size_t)r * D_MODEL;
    #pragma unroll
    for (int i = 0; i < 4; i++) {
        int d = t + i * 256;
        orow[d] = (1.f + sc[d]) * ((v[i] - mean) * inv) + sh[d];
    }
}

// ---------------- tf32 tensor-core GEMM, 64x128x32 tiles, fragment-packed, z-batched ----------------
// epi 0: C = acc;  epi 1: C = gelu(acc + bias);  epi 2: C = res + gate*(acc + bias)
// B fragments pair-packed: adjacent nblk fragments in one 16B group -> LDS.128 loads.
#define TBM 64
#define TBN 128
#define TBK 32
// A fragment store: [oct(4)][mblk(4)][lane(32)][4 words] + pad
#define A_OCT 516           // 4*32*4 + 4  (x4B = 2064, 16B-aligned per oct)
#define A_STAGE (4 * A_OCT)
// B fragment store: [oct(4)][pair(8) stride 132][lane*4 + which*2 + slot]
#define B_PAIR 132
#define B_OCT 1060          // 8*132 + 4 pad (x4B = 4240, 16B-aligned per oct)
#define B_STAGE (4 * B_OCT)
#define GEMM_SMEM ((2 * A_STAGE + 2 * B_STAGE) * 4)   // 50432 bytes

struct BArgs {
    int aoff[3];      // A row offset per z
    int coff[3];      // C row offset per z
    int roff[3];      // res row offset per z
    int m[3];         // rows per z
    long long woff[3];// weight element offset per z
    int boff[3];      // bias element offset per z
    int goff[3];      // gate element offset per z
};

__global__ void __launch_bounds__(256) gemm_tc_kernel(
        const float* __restrict__ A, const float* __restrict__ W,
        float* __restrict__ C, int N, int K,
        const float* __restrict__ bias,
        const float* __restrict__ gate,
        const float* __restrict__ res,
        int epi, BArgs ba) {
    int z = blockIdx.z;
    int brow = blockIdx.y, bcol = blockIdx.x;
    if (brow * TBM >= ba.m[z]) return;

    extern __shared__ uint32_t gsm[];
    uint32_t (*As)[A_STAGE] = (uint32_t(*)[A_STAGE])gsm;
    uint32_t (*Bs)[B_STAGE] = (uint32_t(*)[B_STAGE])(gsm + 2 * A_STAGE);

    int tid  = threadIdx.x;
    int warp = tid >> 5;
    int lane = tid & 31;
    int gid  = lane >> 2;
    int tig  = lane & 3;
    int wm2  = (warp >> 2) * 2;     // mblk base (0 or 2)
    int wp   = (warp & 3) * 2;      // B pair base (0,2,4,6)

    const float* Ab = A + (size_t)ba.aoff[z] * K;
    const float* Bb = W + ba.woff[z];

    // global load mapping: A tile 64x32 = 512 float4 -> 2 per thread
    int al0 = tid, al1 = tid + 256;
    int a_row0 = al0 >> 3, a_kq0 = (al0 & 7) * 4;
    int a_row1 = al1 >> 3, a_kq1 = (al1 & 7) * 4;
    int abase0 = (a_kq0 >> 3) * A_OCT + (a_row0 >> 4) * 128 + (a_row0 & 7) * 16
               + ((a_row0 >> 3) & 1) * 2 + ((a_kq0 >> 2) & 1);
    int abase1 = (a_kq1 >> 3) * A_OCT + (a_row1 >> 4) * 128 + (a_row1 & 7) * 16
               + ((a_row1 >> 3) & 1) * 2 + ((a_kq1 >> 2) & 1);

    // B tile 32x128 = 2048 float2 -> 8 per thread; k rows b_row + r*4, r=0..7
    int b_row = tid >> 6;              // 0..3
    int b_col = (tid & 63) * 2;        // 0..126 (even)

    const float* Aptr0 = Ab + (size_t)(brow * TBM + a_row0) * K + a_kq0;
    const float* Aptr1 = Ab + (size_t)(brow * TBM + a_row1) * K + a_kq1;
    const float* Bptr  = Bb + (size_t)b_row * N + bcol * TBN + b_col;

    // precomputed B store word offsets (within oct) for n = b_col and b_col+1
    // word(n,k) = (n>>4)*132 + ((n&7)*4 + (k&3))*4 + ((n>>3)&1)*2 + (k>>2 within oct)
    int bw0_base = (b_col >> 4) * B_PAIR + ((b_col & 7) * 4) * 4 + ((b_col >> 3) & 1) * 2;
    int n1 = b_col + 1;
    int bw1_base = (n1 >> 4) * B_PAIR + ((n1 & 7) * 4) * 4 + ((n1 >> 3) & 1) * 2;

    float acc[2][4][4];
    #pragma unroll
    for (int i = 0; i < 2; i++)
        #pragma unroll
        for (int j = 0; j < 4; j++)
            #pragma unroll
            for (int c = 0; c < 4; c++) acc[i][j][c] = 0.f;

    int iters = K / TBK;

    float4 av0 = *(const float4*)(Aptr0);
    float4 av1 = *(const float4*)(Aptr1);
    float2 bv[8];
    #pragma unroll
    for (int r = 0; r < 8; r++)
        bv[r] = *(const float2*)(Bptr + (size_t)(r * 4) * N);

    // store tile into fragment layout (raw f32 bits; HMMA truncates to tf32)
    #define STORE_TILE(BUF) do {                                                     \
        As[BUF][abase0 + 0]  = __float_as_uint(av0.x);                               \
        As[BUF][abase0 + 4]  = __float_as_uint(av0.y);                               \
        As[BUF][abase0 + 8]  = __float_as_uint(av0.z);                               \
        As[BUF][abase0 + 12] = __float_as_uint(av0.w);                               \
        As[BUF][abase1 + 0]  = __float_as_uint(av1.x);                               \
        As[BUF][abase1 + 4]  = __float_as_uint(av1.y);                               \
        As[BUF][abase1 + 8]  = __float_as_uint(av1.z);                               \
        As[BUF][abase1 + 12] = __float_as_uint(av1.w);                               \
        _Pragma("unroll")                                                            \
        for (int r = 0; r < 8; r++) {                                                \
            int k   = b_row + r * 4;                                                 \
            int oct = k >> 3;                                                        \
            int j   = k & 7;                                                         \
            int jw  = (j & 3) * 4 + (j >> 2);                                        \
            uint32_t* bb = &Bs[BUF][oct * B_OCT];                                    \
            bb[bw0_base + jw] = __float_as_uint(bv[r].x);                            \
            bb[bw1_base + jw] = __float_as_uint(bv[r].y);                            \
        }                                                                            \
    } while (0)

    STORE_TILE(0);
    __syncthreads();

    for (int it = 0; it < iters; ++it) {
        int cur = it & 1;
        if (it + 1 < iters) {
            int k0 = (it + 1) * TBK;
            av0 = *(const float4*)(Aptr0 + k0);
            av1 = *(const float4*)(Aptr1 + k0);
            #pragma unroll
            for (int r = 0; r < 8; r++)
                bv[r] = *(const float2*)(Bptr + (size_t)(k0 + r * 4) * N);
        }

        #pragma unroll
        for (int oct = 0; oct < 4; oct++) {
            uint4 ua[2];
            #pragma unroll
            for (int mt = 0; mt < 2; mt++)
                ua[mt] = *(const uint4*)&As[cur][oct * A_OCT + (wm2 + mt) * 128 + lane * 4];
            uint4 ubp[2];
            #pragma unroll
            for (int p = 0; p < 2; p++)
                ubp[p] = *(const uint4*)&Bs[cur][oct * B_OCT + (wp + p) * B_PAIR + lane * 4];
            #pragma unroll
            for (int mt = 0; mt < 2; mt++) {
                mma_tf32(acc[mt][0][0], acc[mt][0][1], acc[mt][0][2], acc[mt][0][3],
                         ua[mt].x, ua[mt].z, ua[mt].y, ua[mt].w, ubp[0].x, ubp[0].y);
                mma_tf32(acc[mt][1][0], acc[mt][1][1], acc[mt][1][2], acc[mt][1][3],
                         ua[mt].x, ua[mt].z, ua[mt].y, ua[mt].w, ubp[0].z, ubp[0].w);
                mma_tf32(acc[mt][2][0], acc[mt][2][1], acc[mt][2][2], acc[mt][2][3],
                         ua[mt].x, ua[mt].z, ua[mt].y, ua[mt].w, ubp[1].x, ubp[1].y);
                mma_tf32(acc[mt][3][0], acc[mt][3][1], acc[mt][3][2], acc[mt][3][3],
                         ua[mt].x, ua[mt].z, ua[mt].y, ua[mt].w, ubp[1].z, ubp[1].w);
            }
        }

        if (it + 1 < iters) {
            int nxt = cur ^ 1;
            STORE_TILE(nxt);
            __syncthreads();
        }
    }
    #undef STORE_TILE

    // epilogue
    int wm = (warp >> 2) * 32;
    int wn = (warp & 3) * 32;
    int crow = ba.coff[z];
    int rrow = ba.roff[z];
    int bo = ba.boff[z], go = ba.goff[z];
    #pragma unroll
    for (int mt = 0; mt < 2; mt++) {
        int lrow0 = brow * TBM + wm + mt * 16 + gid;
        int lrow1 = lrow0 + 8;
        #pragma unroll
        for (int nt = 0; nt < 4; nt++) {
            int col0 = bcol * TBN + wn + nt * 8 + tig * 2;
            int col1 = col0 + 1;
            float v0 = acc[mt][nt][0], v1 = acc[mt][nt][1];
            float v2 = acc[mt][nt][2], v3 = acc[mt][nt][3];
            if (epi == 1) {
                v0 = gelu_tanh(v0 + bias[bo + col0]); v1 = gelu_tanh(v1 + bias[bo + col1]);
                v2 = gelu_tanh(v2 + bias[bo + col0]); v3 = gelu_tanh(v3 + bias[bo + col1]);
            } else if (epi == 2) {
                v0 = res[(size_t)(rrow + lrow0) * N + col0] + gate[go + col0] * (v0 + bias[bo + col0]);
                v1 = res[(size_t)(rrow + lrow0) * N + col1] + gate[go + col1] * (v1 + bias[bo + col1]);
                v2 = res[(size_t)(rrow + lrow1) * N + col0] + gate[go + col0] * (v2 + bias[bo + col0]);
                v3 = res[(size_t)(rrow + lrow1) * N + col1] + gate[go + col1] * (v3 + bias[bo + col1]);
            }
            C[(size_t)(crow + lrow0) * N + col0] = v0;
            C[(size_t)(crow + lrow0) * N + col1] = v1;
            C[(size_t)(crow + lrow1) * N + col0] = v2;
            C[(size_t)(crow + lrow1) * N + col1] = v3;
        }
    }
}

// ---------------- QKV post: RMS + scale + RoPE + scatter to head-major ----------------
__global__ void qkvpost_kernel(const float* __restrict__ Y, const float* __restrict__ pe,
                               const float* __restrict__ q_scale, const float* __restrict__ k_scale,
                               float* __restrict__ Q, float* __restrict__ K, float* __restrict__ V) {
    int gw = blockIdx.x * 8 + (threadIdx.x >> 5);   // warp id: 0 .. 2304*16-1
    int lane = threadIdx.x & 31;
    int l = gw >> 4;
    int h = gw & 15;
    int i = (l < L_TXT) ? 2 : (l < (L_TXT + L_IMG) ? 0 : 1);
    bool is_tmp = (l >= L_TXT + L_IMG);

    const float* row = Y + (size_t)l * 3072 + h * HD;
    float q0 = row[2 * lane],        q1 = row[2 * lane + 1];
    float k0 = row[1024 + 2 * lane], k1 = row[1024 + 2 * lane + 1];
    float v0 = row[2048 + 2 * lane], v1 = row[2048 + 2 * lane + 1];

    float qs = q0 * q0 + q1 * q1;
    float ks = k0 * k0 + k1 * k1;
    #pragma unroll
    for (int o = 16; o; o >>= 1) {
        qs += __shfl_xor_sync(0xffffffffu, qs, o);
        ks += __shfl_xor_sync(0xffffffffu, ks, o);
    }
    float qinv = rsqrtf(qs * (1.f / HD) + EPS);
    float kinv = rsqrtf(ks * (1.f / HD) + EPS);

    float qn0 = q0 * qinv * q_scale[i * HD + 2 * lane];
    float qn1 = q1 * qinv * q_scale[i * HD + 2 * lane + 1];
    float kn0 = k0 * kinv * k_scale[i * HD + 2 * lane];
    float kn1 = k1 * kinv * k_scale[i * HD + 2 * lane + 1];

    const float* p = pe + ((size_t)l * 32 + lane) * 4;
    float p00 = p[0], p01 = p[1], p10 = p[2], p11 = p[3];

    size_t base = ((size_t)h * L_ALL + l) * HD + 2 * lane;
    Q[base]     = p00 * qn0 + p01 * qn1;
    Q[base + 1] = p10 * qn0 + p11 * qn1;
    K[base]     = p00 * kn0 + p01 * kn1;
    K[base + 1] = p10 * kn0 + p11 * kn1;
    if (is_tmp) { V[base] = qn0; V[base + 1] = qn1; }
    else        { V[base] = v0;  V[base + 1] = v1;  }
}

// ---------------- flash attention on tensor cores (tf32 mma) ----------------
#define ATQ 64
#define ATK 64
#define ALD 68

__global__ void __launch_bounds__(128) attn_tc_kernel(
        const float* __restrict__ Q, const float* __restrict__ K,
        const float* __restrict__ V, float* __restrict__ Aout) {
    extern __shared__ uint32_t dyn[];
    uint32_t (*Ks)[ALD] = (uint32_t(*)[ALD])dyn;
    uint32_t (*Vs)[ALD] = (uint32_t(*)[ALD])(dyn + ATK * ALD);
    uint32_t (*Ps)[ALD] = (uint32_t(*)[ALD])(dyn + 2 * ATK * ALD);

    int h   = blockIdx.y;
    int q0  = blockIdx.x * ATQ;
    int tid = threadIdx.x;          // 128
    int warp = tid >> 5;
    int lane = tid & 31;
    int gid  = lane >> 2;
    int tig  = lane & 3;
    int w16  = warp * 16;

    const float* Qh = Q + (size_t)h * L_ALL * HD;
    const float* Kh = K + (size_t)h * L_ALL * HD;
    const float* Vh = V + (size_t)h * L_ALL * HD;

    #pragma unroll
    for (int i = 0; i < 8; i++) {
        int linear = tid + i * 128;
        int r = linear >> 4;
        int c4 = (linear & 15) * 4;
        float4 qv = *(const float4*)(Qh + (size_t)(q0 + r) * HD + c4);
        Ps[r][c4 + 0] = f2tf32(qv.x * ATTN_SCALE);
        Ps[r][c4 + 1] = f2tf32(qv.y * ATTN_SCALE);
        Ps[r][c4 + 2] = f2tf32(qv.z * ATTN_SCALE);
        Ps[r][c4 + 3] = f2tf32(qv.w * ATTN_SCALE);
    }
    __syncthreads();

    uint32_t qf[8][4];
    #pragma unroll
    for (int ks = 0; ks < 8; ks++) {
        qf[ks][0] = Ps[w16 + gid][ks * 8 + tig];
        qf[ks][1] = Ps[w16 + gid + 8][ks * 8 + tig];
        qf[ks][2] = Ps[w16 + gid][ks * 8 + tig + 4];
        qf[ks][3] = Ps[w16 + gid + 8][ks * 8 + tig + 4];
    }

    float oacc[8][4];
    #pragma unroll
    for (int nt = 0; nt < 8; nt++)
        #pragma unroll
        for (int c = 0; c < 4; c++) oacc[nt][c] = 0.f;
    float m0 = -INFINITY, m1 = -INFINITY, l0 = 0.f, l1 = 0.f;

    for (int kb = 0; kb < L_ALL; kb += ATK) {
        __syncthreads();
        #pragma unroll
        for (int i = 0; i < 8; i++) {
            int linear = tid + i * 128;
            int r = linear >> 4;
            int c4 = (linear & 15) * 4;
            float4 kv = *(const float4*)(Kh + (size_t)(kb + r) * HD + c4);
            float4 vv = *(const float4*)(Vh + (size_t)(kb + r) * HD + c4);
            Ks[r][c4 + 0] = f2tf32(kv.x); Ks[r][c4 + 1] = f2tf32(kv.y);
            Ks[r][c4 + 2] = f2tf32(kv.z); Ks[r][c4 + 3] = f2tf32(kv.w);
            Vs[r][c4 + 0] = f2tf32(vv.x); Vs[r][c4 + 1] = f2tf32(vv.y);
            Vs[r][c4 + 2] = f2tf32(vv.z); Vs[r][c4 + 3] = f2tf32(vv.w);
        }
        __syncthreads();

        float sacc[8][4];
        #pragma unroll
        for (int nt = 0; nt < 8; nt++)
            #pragma unroll
            for (int c = 0; c < 4; c++) sacc[nt][c] = 0.f;
        #pragma unroll
        for (int ks = 0; ks < 8; ks++) {
            #pragma unroll
            for (int nt = 0; nt < 8; nt++) {
                uint32_t b0 = Ks[nt * 8 + gid][ks * 8 + tig];
                uint32_t b1 = Ks[nt * 8 + gid][ks * 8 + tig + 4];
                mma_tf32(sacc[nt][0], sacc[nt][1], sacc[nt][2], sacc[nt][3],
                         qf[ks][0], qf[ks][1], qf[ks][2], qf[ks][3], b0, b1);
            }
        }

        float t0 = -INFINITY, t1 = -INFINITY;
        #pragma unroll
        for (int nt = 0; nt < 8; nt++) {
            t0 = fmaxf(t0, fmaxf(sacc[nt][0], sacc[nt][1]));
            t1 = fmaxf(t1, fmaxf(sacc[nt][2], sacc[nt][3]));
        }
        t0 = fmaxf(t0, __shfl_xor_sync(0xffffffffu, t0, 1));
        t0 = fmaxf(t0, __shfl_xor_sync(0xffffffffu, t0, 2));
        t1 = fmaxf(t1, __shfl_xor_sync(0xffffffffu, t1, 1));
        t1 = fmaxf(t1, __shfl_xor_sync(0xffffffffu, t1, 2));
        float mn0 = fmaxf(m0, t0), mn1 = fmaxf(m1, t1);
        float al0 = __expf(m0 - mn0), al1 = __expf(m1 - mn1);
        m0 = mn0; m1 = mn1;

        float ts0 = 0.f, ts1 = 0.f;
        #pragma unroll
        for (int nt = 0; nt < 8; nt++) {
            int c0 = nt * 8 + tig * 2;
            uint32_t p00 = f2tf32(__expf(sacc[nt][0] - mn0));
            uint32_t p01 = f2tf32(__expf(sacc[nt][1] - mn0));
            uint32_t p10 = f2tf32(__expf(sacc[nt][2] - mn1));
            uint32_t p11 = f2tf32(__expf(sacc[nt][3] - mn1));
            Ps[w16 + gid][c0]         = p00;
            Ps[w16 + gid][c0 + 1]     = p01;
            Ps[w16 + gid + 8][c0]     = p10;
            Ps[w16 + gid + 8][c0 + 1] = p11;
            ts0 += __uint_as_float(p00) + __uint_as_float(p01);
            ts1 += __uint_as_float(p10) + __uint_as_float(p11);
        }
        ts0 += __shfl_xor_sync(0xffffffffu, ts0, 1);
        ts0 += __shfl_xor_sync(0xffffffffu, ts0, 2);
        ts1 += __shfl_xor_sync(0xffffffffu, ts1, 1);
        ts1 += __shfl_xor_sync(0xffffffffu, ts1, 2);
        l0 = l0 * al0 + ts0;
        l1 = l1 * al1 + ts1;

        #pragma unroll
        for (int nt = 0; nt < 8; nt++) {
            oacc[nt][0] *= al0; oacc[nt][1] *= al0;
            oacc[nt][2] *= al1; oacc[nt][3] *= al1;
        }
        __syncwarp();

        #pragma unroll
        for (int ks = 0; ks < 8; ks++) {
            uint32_t a0 = Ps[w16 + gid][ks * 8 + tig];
            uint32_t a1 = Ps[w16 + gid + 8][ks * 8 + tig];
            uint32_t a2 = Ps[w16 + gid][ks * 8 + tig + 4];
            uint32_t a3 = Ps[w16 + gid + 8][ks * 8 + tig + 4];
            #pragma unroll
            for (int nt = 0; nt < 8; nt++) {
                uint32_t b0 = Vs[ks * 8 + tig][nt * 8 + gid];
                uint32_t b1 = Vs[ks * 8 + tig + 4][nt * 8 + gid];
                mma_tf32(oacc[nt][0], oacc[nt][1], oacc[nt][2], oacc[nt][3],
                         a0, a1, a2, a3, b0, b1);
            }
        }
        __syncwarp();
    }

    float i0 = 1.f / l0, i1 = 1.f / l1;
    int r0 = q0 + w16 + gid;
    int r1 = r0 + 8;
    #pragma unroll
    for (int nt = 0; nt < 8; nt++) {
        int c0 = h * HD + nt * 8 + tig * 2;
        Aout[(size_t)r0 * D_MODEL + c0]     = oacc[nt][0] * i0;
        Aout[(size_t)r0 * D_MODEL + c0 + 1] = oacc[nt][1] * i0;
        Aout[(size_t)r1 * D_MODEL + c0]     = oacc[nt][2] * i1;
        Aout[(size_t)r1 * D_MODEL + c0 + 1] = oacc[nt][3] * i1;
    }
}

#define ATTN_SMEM (3 * ATK * ALD * 4)

extern "C" void kernel_launch(void* const* d_in, const int* in_sizes, int n_in,
                              void* d_out, int out_size) {
    const float* img      = (const float*)d_in[0];
    const float* temporal = (const float*)d_in[1];
    const float* txt      = (const float*)d_in[2];
    const float* vec      = (const float*)d_in[3];
    const float* pe       = (const float*)d_in[4];
    const float* mod_w    = (const float*)d_in[5];
    const float* mod_b    = (const float*)d_in[6];
    const float* qkv_w    = (const float*)d_in[7];
    const float* q_scale  = (const float*)d_in[8];
    const float* k_scale  = (const float*)d_in[9];
    const float* proj_w   = (const float*)d_in[10];
    const float* proj_b   = (const float*)d_in[11];
    const float* mlp_w1   = (const float*)d_in[12];
    const float* mlp_b1   = (const float*)d_in[13];
    const float* mlp_w2   = (const float*)d_in[14];
    const float* mlp_b2   = (const float*)d_in[15];
    float* out = (float*)d_out;

    static float *mod = 0, *res = 0, *xm = 0, *qkv = 0, *Qb = 0, *Kb = 0, *Vb = 0,
                 *attn = 0, *x1 = 0, *ym = 0, *hbuf = 0;
    if (!mod) {
        cudaGetSymbolAddress((void**)&mod,  g_mod);
        cudaGetSymbolAddress((void**)&res,  g_res);
        cudaGetSymbolAddress((void**)&xm,   g_xm);
        cudaGetSymbolAddress((void**)&qkv,  g_qkv);
        cudaGetSymbolAddress((void**)&Qb,   g_Q);
        cudaGetSymbolAddress((void**)&Kb,   g_K);
        cudaGetSymbolAddress((void**)&Vb,   g_V);
        cudaGetSymbolAddress((void**)&attn, g_attn);
        cudaGetSymbolAddress((void**)&x1,   g_x1);
        cudaGetSymbolAddress((void**)&ym,   g_ym);
        cudaGetSymbolAddress((void**)&hbuf, g_h);
        cudaFuncSetAttribute(attn_tc_kernel,
                             cudaFuncAttributeMaxDynamicSharedMemorySize, ATTN_SMEM);
        cudaFuncSetAttribute(gemm_tc_kernel,
                             cudaFuncAttributeMaxDynamicSharedMemorySize, GEMM_SMEM);
    }

    const int off_txt = 0;
    const int off_img = L_TXT;
    const int off_tmp = L_TXT + L_IMG;

    // Launch order: mod(1) lnmod(2,3,4) QKV(5) -> ncu -s 5 -c 1 captures the GEMM.
    // 1. mod (silu fused)
    mod_kernel<<<(3 * 6144) / 256, 256>>>(vec, mod_w, mod_b, mod);

    // 2. LN1 + modulate
    lnmod_kernel<<<L_TXT, 256>>>(txt,      xm + (size_t)off_txt * D_MODEL, mod + 2 * 6144, mod + 2 * 6144 + 1024);
    lnmod_kernel<<<L_IMG, 256>>>(img,      xm + (size_t)off_img * D_MODEL, mod + 0,        mod + 1024);
    lnmod_kernel<<<L_TMP, 256>>>(temporal, xm + (size_t)off_tmp * D_MODEL, mod + 1 * 6144, mod + 1 * 6144 + 1024);

    // 3. QKV (batched z=3: txt->w2, img->w0, tmp->w1)  [launch #5]
    {
        BArgs ba = {};
        int ao[3] = {off_txt, off_img, off_tmp};
        for (int z = 0; z < 3; z++) { ba.aoff[z] = ao[z]; ba.coff[z] = ao[z]; }
        ba.m[0] = 256; ba.m[1] = 1024; ba.m[2] = 1024;
        ba.woff[0] = 2LL * 1024 * 3072; ba.woff[1] = 0; ba.woff[2] = 1LL * 1024 * 3072;
        gemm_tc_kernel<<<dim3(3072 / TBN, 16, 3), 256, GEMM_SMEM>>>(xm, qkv_w, qkv, 3072, 1024,
                                                                    proj_b, mod, res, 0, ba);
    }

    // 4. residual concat copy (needed first at proj epilogue)
    copy3_kernel<<<(L_ALL * D_MODEL / 4) / 256, 256>>>(txt, img, temporal, res);

    // 5. RMS + scale + RoPE + scatter
    qkvpost_kernel<<<(L_ALL * NH) / 8, 256>>>(qkv, pe, q_scale, k_scale, Qb, Kb, Vb);

    // 6. attention
    attn_tc_kernel<<<dim3(L_ALL / ATQ, NH), 128, ATTN_SMEM>>>(Qb, Kb, Vb, attn);

    // 7. proj + gate + residual (batched z=3)
    {
        BArgs ba = {};
        int ao[3] = {off_txt, off_img, off_tmp};
        int wi[3] = {2, 0, 1};
        for (int z = 0; z < 3; z++) {
            ba.aoff[z] = ao[z]; ba.coff[z] = ao[z]; ba.roff[z] = ao[z];
            ba.woff[z] = (long long)wi[z] * 1024 * 1024;
            ba.boff[z] = wi[z] * 1024;
            ba.goff[z] = wi[z] * 6144 + 2048;
        }
        ba.m[0] = 256; ba.m[1] = 1024; ba.m[2] = 1024;
        gemm_tc_kernel<<<dim3(1024 / TBN, 16, 3), 256, GEMM_SMEM>>>(attn, proj_w, x1, 1024, 1024,
                                                                    proj_b, mod, res, 2, ba);
    }

    // 8. img + txt MLP (batched z=2); temporal must wait for final img
    lnmod_kernel<<<L_IMG, 256>>>(x1 + (size_t)off_img * D_MODEL, ym,
                                 mod + 0 * 6144 + 3072, mod + 0 * 6144 + 4096);
    lnmod_kernel<<<L_TXT, 256>>>(x1 + (size_t)off_txt * D_MODEL, ym + (size_t)1024 * D_MODEL,
                                 mod + 2 * 6144 + 3072, mod + 2 * 6144 + 4096);
    {
        BArgs ba = {};
        ba.aoff[0] = 0;    ba.coff[0] = 0;    ba.m[0] = 1024;
        ba.woff[0] = 0;    ba.boff[0] = 0;
        ba.aoff[1] = 1024; ba.coff[1] = 1024; ba.m[1] = 256;
        ba.woff[1] = 2LL * 1024 * 4096; ba.boff[1] = 2 * 4096;
        gemm_tc_kernel<<<dim3(4096 / TBN, 16, 2), 256, GEMM_SMEM>>>(ym, mlp_w1, hbuf, 4096, 1024,
                                                                    mlp_b1, mod, res, 1, ba);
    }
    {
        BArgs ba = {};
        // z0: img -> out rows [0,1024), res = x1 img rows
        ba.aoff[0] = 0;    ba.coff[0] = 0;    ba.roff[0] = off_img; ba.m[0] = 1024;
        ba.woff[0] = 0;    ba.boff[0] = 0;    ba.goff[0] = 0 * 6144 + 5120;
        // z1: txt -> out rows [2048,2304), res = x1 txt rows
        ba.aoff[1] = 1024; ba.coff[1] = 2048; ba.roff[1] = off_txt; ba.m[1] = 256;
        ba.woff[1] = 2LL * 4096 * 1024; ba.boff[1] = 2 * 1024; ba.goff[1] = 2 * 6144 + 5120;
        gemm_tc_kernel<<<dim3(1024 / TBN, 16, 2), 256, GEMM_SMEM>>>(hbuf, mlp_w2, out, 1024, 4096,
                                                                    mlp_b2, mod, x1, 2, ba);
    }

    // 9. temporal MLP: LN of FINAL img (reference quirk), residual = x1 tmp rows
    lnmod_kernel<<<L_TMP, 256>>>(out, ym, mod + 1 * 6144 + 3072, mod + 1 * 6144 + 4096);
    {
        BArgs ba = {};
        ba.aoff[0] = 0; ba.coff[0] = 0; ba.m[0] = 1024;
        ba.woff[0] = 1LL * 1024 * 4096; ba.boff[0] = 4096;
        gemm_tc_kernel<<<dim3(4096 / TBN, 16, 1), 256, GEMM_SMEM>>>(ym, mlp_w1, hbuf, 4096, 1024,
                                                                    mlp_b1, mod, res, 1, ba);
    }
    {
        BArgs ba = {};
        ba.aoff[0] = 0; ba.coff[0] = 1024; ba.roff[0] = off_tmp; ba.m[0] = 1024;
        ba.woff[0] = 1LL * 4096 * 1024; ba.boff[0] = 1024; ba.goff[0] = 1 * 6144 + 5120;
        gemm_tc_kernel<<<dim3(1024 / TBN, 16, 1), 256, GEMM_SMEM>>>(hbuf, mlp_w2, out, 1024, 4096,
                                                                    mlp_b2, mod, x1, 2, ba);
    }
}

// round 12
// speedup vs baseline: 1.0607x; 1.0607x over previous
#include <cuda_runtime.h>
#include <cuda_bf16.h>
#include <math.h>
#include <stdint.h>

// ---------------- problem constants ----------------
#define L_TXT 256
#define L_IMG 1024
#define L_TMP 1024
#define L_ALL 2304          // txt + img + tmp
#define D_MODEL 1024
#define NH 16
#define HD 64
#define D_MLP 4096
#define EPS 1e-6f
#define ATTN_SCALE 0.125f   // 1/sqrt(64)

// ---------------- scratch (static device memory; no allocation) ----------------
__device__ float g_mod[3 * 6144];
__device__ float g_xm[L_ALL * D_MODEL];        // LN1-modulated, concat order [txt|img|tmp]
__device__ float g_qkv[L_ALL * 3 * D_MODEL];   // QKV gemm out, same row order
__device__ float g_Q[NH * L_ALL * HD];
__device__ float g_K[NH * L_ALL * HD];
__device__ float g_V[NH * L_ALL * HD];
__device__ float g_attn[L_ALL * D_MODEL];      // [l][h*64+d], concat order
__device__ float g_x1[L_ALL * D_MODEL];        // post-proj residual, concat order
__device__ float g_ym[1280 * D_MODEL];         // LN2-modulated (img rows 0..1023, txt rows 1024..1279)
__device__ float g_h[1280 * D_MLP];            // MLP hidden

// ---------------- helpers ----------------
__device__ __forceinline__ float gelu_tanh(float x) {
    const float c = 0.7978845608028654f; // sqrt(2/pi)
    float x3 = x * x * x;
    return 0.5f * x * (1.f + tanhf(c * (x + 0.044715f * x3)));
}

__device__ __forceinline__ uint32_t f2tf32(float f) {
    uint32_t u;
    asm("cvt.rna.tf32.f32 %0, %1;" : "=r"(u) : "f"(f));
    return u;
}

__device__ __forceinline__ void mma_tf32(float& d0, float& d1, float& d2, float& d3,
                                         uint32_t a0, uint32_t a1, uint32_t a2, uint32_t a3,
                                         uint32_t b0, uint32_t b1) {
    asm volatile(
        "mma.sync.aligned.m16n8k8.row.col.f32.tf32.tf32.f32 "
        "{%0,%1,%2,%3}, {%4,%5,%6,%7}, {%8,%9}, {%0,%1,%2,%3};"
        : "+f"(d0), "+f"(d1), "+f"(d2), "+f"(d3)
        : "r"(a0), "r"(a1), "r"(a2), "r"(a3), "r"(b0), "r"(b1));
}

// ---------------- mod = silu(vec) @ mod_w + mod_b  (3 x 6144 outputs; silu fused) ----------------
__global__ void mod_kernel(const float* __restrict__ vecp, const float* __restrict__ mod_w,
                           const float* __restrict__ mod_b, float* __restrict__ mod) {
    __shared__ float s_sv[D_MODEL];
    for (int i = threadIdx.x; i < D_MODEL; i += 256) {
        float x = vecp[i];
        s_sv[i] = x / (1.f + expf(-x));
    }
    __syncthreads();
    int o = blockIdx.x * 256 + threadIdx.x;       // 0 .. 3*6144-1
    int i = o / 6144;
    int j = o - i * 6144;
    const float* w = mod_w + (size_t)i * D_MODEL * 6144 + j;
    float acc = 0.f;
    #pragma unroll 8
    for (int d = 0; d < D_MODEL; ++d) acc = fmaf(s_sv[d], w[(size_t)d * 6144], acc);
    mod[o] = acc + mod_b[o];
}

// ---------------- LN + modulate: out = (1+sc)*ln(x) + sh ----------------
__global__ void lnmod_kernel(const float* __restrict__ x, float* __restrict__ out,
                             const float* __restrict__ sh, const float* __restrict__ sc) {
    int r = blockIdx.x;
    const float* xr = x + (size_t)r * D_MODEL;
    int t = threadIdx.x; // 256
    float v[4]; float sum = 0.f, sq = 0.f;
    #pragma unroll
    for (int i = 0; i < 4; i++) { float f = xr[t + i * 256]; v[i] = f; sum += f; sq += f * f; }
    #pragma unroll
    for (int o = 16; o; o >>= 1) {
        sum += __shfl_xor_sync(0xffffffffu, sum, o);
        sq  += __shfl_xor_sync(0xffffffffu, sq, o);
    }
    __shared__ float ssum[8], ssq[8];
    int w = t >> 5, lane = t & 31;
    if (lane == 0) { ssum[w] = sum; ssq[w] = sq; }
    __syncthreads();
    if (t == 0) {
        float S = 0.f, Q = 0.f;
        #pragma unroll
        for (int i = 0; i < 8; i++) { S += ssum[i]; Q += ssq[i]; }
        float mean = S * (1.f / D_MODEL);
        float var  = Q * (1.f / D_MODEL) - mean * mean;
        ssum[0] = mean; ssq[0] = rsqrtf(var + EPS);
    }
    __syncthreads();
    float mean = ssum[0], inv = ssq[0];
    float* orow = out + (size_t)r * D_MODEL;
    #pragma unroll
    for (int i = 0; i < 4; i++) {
        int d = t + i * 256;
        orow[d] = (1.f + sc[d]) * ((v[i] - mean) * inv) + sh[d];
    }
}

// ---------------- tf32 tensor-core GEMM, 64x128x32 tiles, fragment-packed, z-batched ----------------
// epi 0: C = acc;  epi 1: C = gelu(acc + bias);  epi 2: C = resp[z] + gate*(acc + bias)
// Staging buffers in DYNAMIC smem (50368 B). Proven B_NB=66 layout (round-8 best).
#define TBM 64
#define TBN 128
#define TBK 32
// A fragment store: [oct(4)][mblk(4)][lane(32)][4 words] + pad
#define A_OCT 516           // 4*32*4 + 4
#define A_STAGE (4 * A_OCT)
// B fragment store: [oct(4)][nblk(16) stride 66][lane*2 + slot]
#define B_NB 66
#define B_OCT 1058          // 16*66 + 2
#define B_STAGE (4 * B_OCT)
#define GEMM_SMEM ((2 * A_STAGE + 2 * B_STAGE) * 4)   // 50368 bytes

struct BArgs {
    const float* resp[3]; // residual base pointer per z (epi 2)
    int aoff[3];      // A row offset per z
    int coff[3];      // C row offset per z
    int roff[3];      // res row offset per z (applied to resp[z])
    int m[3];         // rows per z
    long long woff[3];// weight element offset per z
    int boff[3];      // bias element offset per z
    int goff[3];      // gate element offset per z
};

__global__ void __launch_bounds__(256) gemm_tc_kernel(
        const float* __restrict__ A, const float* __restrict__ W,
        float* __restrict__ C, int N, int K,
        const float* __restrict__ bias,
        const float* __restrict__ gate,
        int epi, BArgs ba) {
    int z = blockIdx.z;
    int brow = blockIdx.y, bcol = blockIdx.x;
    if (brow * TBM >= ba.m[z]) return;

    extern __shared__ uint32_t gsm[];
    uint32_t (*As)[A_STAGE] = (uint32_t(*)[A_STAGE])gsm;
    uint32_t (*Bs)[B_STAGE] = (uint32_t(*)[B_STAGE])(gsm + 2 * A_STAGE);

    int tid  = threadIdx.x;
    int warp = tid >> 5;
    int lane = tid & 31;
    int gid  = lane >> 2;
    int tig  = lane & 3;
    int wm2  = (warp >> 2) * 2;     // mblk base (0 or 2)
    int wn8  = (warp & 3) * 4;      // nblk base

    const float* Ab = A + (size_t)ba.aoff[z] * K;
    const float* Bb = W + ba.woff[z];

    // global load mapping: A tile 64x32 = 512 float4 -> 2 per thread
    int al0 = tid, al1 = tid + 256;
    int a_row0 = al0 >> 3, a_kq0 = (al0 & 7) * 4;
    int a_row1 = al1 >> 3, a_kq1 = (al1 & 7) * 4;
    int abase0 = (a_kq0 >> 3) * A_OCT + (a_row0 >> 4) * 128 + (a_row0 & 7) * 16
               + ((a_row0 >> 3) & 1) * 2 + ((a_kq0 >> 2) & 1);
    int abase1 = (a_kq1 >> 3) * A_OCT + (a_row1 >> 4) * 128 + (a_row1 & 7) * 16
               + ((a_row1 >> 3) & 1) * 2 + ((a_kq1 >> 2) & 1);

    // B tile 32x128 = 2048 float2 -> 8 per thread; k rows b_row + r*4, r=0..7
    int b_row = tid >> 6;              // 0..3
    int b_col = (tid & 63) * 2;        // 0..126

    const float* Aptr0 = Ab + (size_t)(brow * TBM + a_row0) * K + a_kq0;
    const float* Aptr1 = Ab + (size_t)(brow * TBM + a_row1) * K + a_kq1;
    const float* Bptr  = Bb + (size_t)b_row * N + bcol * TBN + b_col;

    float acc[2][4][4];
    #pragma unroll
    for (int i = 0; i < 2; i++)
        #pragma unroll
        for (int j = 0; j < 4; j++)
            #pragma unroll
            for (int c = 0; c < 4; c++) acc[i][j][c] = 0.f;

    int iters = K / TBK;

    float4 av0 = *(const float4*)(Aptr0);
    float4 av1 = *(const float4*)(Aptr1);
    float2 bv[8];
    #pragma unroll
    for (int r = 0; r < 8; r++)
        bv[r] = *(const float2*)(Bptr + (size_t)(r * 4) * N);

    // store tile into fragment layout (raw f32 bits; HMMA truncates to tf32)
    #define STORE_TILE(BUF) do {                                                     \
        As[BUF][abase0 + 0]  = __float_as_uint(av0.x);                               \
        As[BUF][abase0 + 4]  = __float_as_uint(av0.y);                               \
        As[BUF][abase0 + 8]  = __float_as_uint(av0.z);                               \
        As[BUF][abase0 + 12] = __float_as_uint(av0.w);                               \
        As[BUF][abase1 + 0]  = __float_as_uint(av1.x);                               \
        As[BUF][abase1 + 4]  = __float_as_uint(av1.y);                               \
        As[BUF][abase1 + 8]  = __float_as_uint(av1.z);                               \
        As[BUF][abase1 + 12] = __float_as_uint(av1.w);                               \
        _Pragma("unroll")                                                            \
        for (int r = 0; r < 8; r++) {                                                \
            int k   = b_row + r * 4;                                                 \
            int oct = k >> 3;                                                        \
            int j   = k & 7;                                                         \
            int jm  = j & 3;                                                         \
            int sl  = j >> 2;                                                        \
            int n7  = b_col & 7;                                                     \
            int nbl = b_col >> 3;                                                    \
            uint32_t* bb = &Bs[BUF][oct * B_OCT + nbl * B_NB + sl];                  \
            bb[(n7 * 4 + jm) * 2]       = __float_as_uint(bv[r].x);                  \
            bb[((n7 + 1) * 4 + jm) * 2] = __float_as_uint(bv[r].y);                  \
        }                                                                            \
    } while (0)

    STORE_TILE(0);
    __syncthreads();

    for (int it = 0; it < iters; ++it) {
        int cur = it & 1;
        if (it + 1 < iters) {
            int k0 = (it + 1) * TBK;
            av0 = *(const float4*)(Aptr0 + k0);
            av1 = *(const float4*)(Aptr1 + k0);
            #pragma unroll
            for (int r = 0; r < 8; r++)
                bv[r] = *(const float2*)(Bptr + (size_t)(k0 + r * 4) * N);
        }

        #pragma unroll
        for (int oct = 0; oct < 4; oct++) {
            uint4 ua[2];
            #pragma unroll
            for (int mt = 0; mt < 2; mt++)
                ua[mt] = *(const uint4*)&As[cur][oct * A_OCT + (wm2 + mt) * 128 + lane * 4];
            uint2 ub[4];
            #pragma unroll
            for (int nt = 0; nt < 4; nt++)
                ub[nt] = *(const uint2*)&Bs[cur][oct * B_OCT + (wn8 + nt) * B_NB + lane * 2];
            #pragma unroll
            for (int mt = 0; mt < 2; mt++)
                #pragma unroll
                for (int nt = 0; nt < 4; nt++)
                    mma_tf32(acc[mt][nt][0], acc[mt][nt][1], acc[mt][nt][2], acc[mt][nt][3],
                             ua[mt].x, ua[mt].z, ua[mt].y, ua[mt].w,
                             ub[nt].x, ub[nt].y);
        }

        if (it + 1 < iters) {
            int nxt = cur ^ 1;
            STORE_TILE(nxt);
            __syncthreads();
        }
    }
    #undef STORE_TILE

    // epilogue
    int wm = (warp >> 2) * 32;
    int wn = (warp & 3) * 32;
    int crow = ba.coff[z];
    int rrow = ba.roff[z];
    const float* resz = ba.resp[z];
    int bo = ba.boff[z], go = ba.goff[z];
    #pragma unroll
    for (int mt = 0; mt < 2; mt++) {
        int lrow0 = brow * TBM + wm + mt * 16 + gid;
        int lrow1 = lrow0 + 8;
        #pragma unroll
        for (int nt = 0; nt < 4; nt++) {
            int col0 = bcol * TBN + wn + nt * 8 + tig * 2;
            int col1 = col0 + 1;
            float v0 = acc[mt][nt][0], v1 = acc[mt][nt][1];
            float v2 = acc[mt][nt][2], v3 = acc[mt][nt][3];
            if (epi == 1) {
                v0 = gelu_tanh(v0 + bias[bo + col0]); v1 = gelu_tanh(v1 + bias[bo + col1]);
                v2 = gelu_tanh(v2 + bias[bo + col0]); v3 = gelu_tanh(v3 + bias[bo + col1]);
            } else if (epi == 2) {
                v0 = resz[(size_t)(rrow + lrow0) * N + col0] + gate[go + col0] * (v0 + bias[bo + col0]);
                v1 = resz[(size_t)(rrow + lrow0) * N + col1] + gate[go + col1] * (v1 + bias[bo + col1]);
                v2 = resz[(size_t)(rrow + lrow1) * N + col0] + gate[go + col0] * (v2 + bias[bo + col0]);
                v3 = resz[(size_t)(rrow + lrow1) * N + col1] + gate[go + col1] * (v3 + bias[bo + col1]);
            }
            C[(size_t)(crow + lrow0) * N + col0] = v0;
            C[(size_t)(crow + lrow0) * N + col1] = v1;
            C[(size_t)(crow + lrow1) * N + col0] = v2;
            C[(size_t)(crow + lrow1) * N + col1] = v3;
        }
    }
}

// ---------------- QKV post: RMS + scale + RoPE + scatter to head-major ----------------
__global__ void qkvpost_kernel(const float* __restrict__ Y, const float* __restrict__ pe,
                               const float* __restrict__ q_scale, const float* __restrict__ k_scale,
                               float* __restrict__ Q, float* __restrict__ K, float* __restrict__ V) {
    int gw = blockIdx.x * 8 + (threadIdx.x >> 5);   // warp id: 0 .. 2304*16-1
    int lane = threadIdx.x & 31;
    int l = gw >> 4;
    int h = gw & 15;
    int i = (l < L_TXT) ? 2 : (l < (L_TXT + L_IMG) ? 0 : 1);
    bool is_tmp = (l >= L_TXT + L_IMG);

    const float* row = Y + (size_t)l * 3072 + h * HD;
    float q0 = row[2 * lane],        q1 = row[2 * lane + 1];
    float k0 = row[1024 + 2 * lane], k1 = row[1024 + 2 * lane + 1];
    float v0 = row[2048 + 2 * lane], v1 = row[2048 + 2 * lane + 1];

    float qs = q0 * q0 + q1 * q1;
    float ks = k0 * k0 + k1 * k1;
    #pragma unroll
    for (int o = 16; o; o >>= 1) {
        qs += __shfl_xor_sync(0xffffffffu, qs, o);
        ks += __shfl_xor_sync(0xffffffffu, ks, o);
    }
    float qinv = rsqrtf(qs * (1.f / HD) + EPS);
    float kinv = rsqrtf(ks * (1.f / HD) + EPS);

    float qn0 = q0 * qinv * q_scale[i * HD + 2 * lane];
    float qn1 = q1 * qinv * q_scale[i * HD + 2 * lane + 1];
    float kn0 = k0 * kinv * k_scale[i * HD + 2 * lane];
    float kn1 = k1 * kinv * k_scale[i * HD + 2 * lane + 1];

    const float* p = pe + ((size_t)l * 32 + lane) * 4;
    float p00 = p[0], p01 = p[1], p10 = p[2], p11 = p[3];

    size_t base = ((size_t)h * L_ALL + l) * HD + 2 * lane;
    Q[base]     = p00 * qn0 + p01 * qn1;
    Q[base + 1] = p10 * qn0 + p11 * qn1;
    K[base]     = p00 * kn0 + p01 * kn1;
    K[base + 1] = p10 * kn0 + p11 * kn1;
    if (is_tmp) { V[base] = qn0; V[base + 1] = qn1; }
    else        { V[base] = v0;  V[base + 1] = v1;  }
}

// ---------------- flash attention on tensor cores (tf32 mma) ----------------
#define ATQ 64
#define ATK 64
#define ALD 68

__global__ void __launch_bounds__(128) attn_tc_kernel(
        const float* __restrict__ Q, const float* __restrict__ K,
        const float* __restrict__ V, float* __restrict__ Aout) {
    extern __shared__ uint32_t dyn[];
    uint32_t (*Ks)[ALD] = (uint32_t(*)[ALD])dyn;
    uint32_t (*Vs)[ALD] = (uint32_t(*)[ALD])(dyn + ATK * ALD);
    uint32_t (*Ps)[ALD] = (uint32_t(*)[ALD])(dyn + 2 * ATK * ALD);

    int h   = blockIdx.y;
    int q0  = blockIdx.x * ATQ;
    int tid = threadIdx.x;          // 128
    int warp = tid >> 5;
    int lane = tid & 31;
    int gid  = lane >> 2;
    int tig  = lane & 3;
    int w16  = warp * 16;

    const float* Qh = Q + (size_t)h * L_ALL * HD;
    const float* Kh = K + (size_t)h * L_ALL * HD;
    const float* Vh = V + (size_t)h * L_ALL * HD;

    #pragma unroll
    for (int i = 0; i < 8; i++) {
        int linear = tid + i * 128;
        int r = linear >> 4;
        int c4 = (linear & 15) * 4;
        float4 qv = *(const float4*)(Qh + (size_t)(q0 + r) * HD + c4);
        Ps[r][c4 + 0] = f2tf32(qv.x * ATTN_SCALE);
        Ps[r][c4 + 1] = f2tf32(qv.y * ATTN_SCALE);
        Ps[r][c4 + 2] = f2tf32(qv.z * ATTN_SCALE);
        Ps[r][c4 + 3] = f2tf32(qv.w * ATTN_SCALE);
    }
    __syncthreads();

    uint32_t qf[8][4];
    #pragma unroll
    for (int ks = 0; ks < 8; ks++) {
        qf[ks][0] = Ps[w16 + gid][ks * 8 + tig];
        qf[ks][1] = Ps[w16 + gid + 8][ks * 8 + tig];
        qf[ks][2] = Ps[w16 + gid][ks * 8 + tig + 4];
        qf[ks][3] = Ps[w16 + gid + 8][ks * 8 + tig + 4];
    }

    float oacc[8][4];
    #pragma unroll
    for (int nt = 0; nt < 8; nt++)
        #pragma unroll
        for (int c = 0; c < 4; c++) oacc[nt][c] = 0.f;
    float m0 = -INFINITY, m1 = -INFINITY, l0 = 0.f, l1 = 0.f;

    for (int kb = 0; kb < L_ALL; kb += ATK) {
        __syncthreads();
        #pragma unroll
        for (int i = 0; i < 8; i++) {
            int linear = tid + i * 128;
            int r = linear >> 4;
            int c4 = (linear & 15) * 4;
            float4 kv = *(const float4*)(Kh + (size_t)(kb + r) * HD + c4);
            float4 vv = *(const float4*)(Vh + (size_t)(kb + r) * HD + c4);
            Ks[r][c4 + 0] = f2tf32(kv.x); Ks[r][c4 + 1] = f2tf32(kv.y);
            Ks[r][c4 + 2] = f2tf32(kv.z); Ks[r][c4 + 3] = f2tf32(kv.w);
            Vs[r][c4 + 0] = f2tf32(vv.x); Vs[r][c4 + 1] = f2tf32(vv.y);
            Vs[r][c4 + 2] = f2tf32(vv.z); Vs[r][c4 + 3] = f2tf32(vv.w);
        }
        __syncthreads();

        float sacc[8][4];
        #pragma unroll
        for (int nt = 0; nt < 8; nt++)
            #pragma unroll
            for (int c = 0; c < 4; c++) sacc[nt][c] = 0.f;
        #pragma unroll
        for (int ks = 0; ks < 8; ks++) {
            #pragma unroll
            for (int nt = 0; nt < 8; nt++) {
                uint32_t b0 = Ks[nt * 8 + gid][ks * 8 + tig];
                uint32_t b1 = Ks[nt * 8 + gid][ks * 8 + tig + 4];
                mma_tf32(sacc[nt][0], sacc[nt][1], sacc[nt][2], sacc[nt][3],
                         qf[ks][0], qf[ks][1], qf[ks][2], qf[ks][3], b0, b1);
            }
        }

        float t0 = -INFINITY, t1 = -INFINITY;
        #pragma unroll
        for (int nt = 0; nt < 8; nt++) {
            t0 = fmaxf(t0, fmaxf(sacc[nt][0], sacc[nt][1]));
            t1 = fmaxf(t1, fmaxf(sacc[nt][2], sacc[nt][3]));
        }
        t0 = fmaxf(t0, __shfl_xor_sync(0xffffffffu, t0, 1));
        t0 = fmaxf(t0, __shfl_xor_sync(0xffffffffu, t0, 2));
        t1 = fmaxf(t1, __shfl_xor_sync(0xffffffffu, t1, 1));
        t1 = fmaxf(t1, __shfl_xor_sync(0xffffffffu, t1, 2));
        float mn0 = fmaxf(m0, t0), mn1 = fmaxf(m1, t1);
        float al0 = __expf(m0 - mn0), al1 = __expf(m1 - mn1);
        m0 = mn0; m1 = mn1;

        float ts0 = 0.f, ts1 = 0.f;
        #pragma unroll
        for (int nt = 0; nt < 8; nt++) {
            int c0 = nt * 8 + tig * 2;
            uint32_t p00 = f2tf32(__expf(sacc[nt][0] - mn0));
            uint32_t p01 = f2tf32(__expf(sacc[nt][1] - mn0));
            uint32_t p10 = f2tf32(__expf(sacc[nt][2] - mn1));
            uint32_t p11 = f2tf32(__expf(sacc[nt][3] - mn1));
            Ps[w16 + gid][c0]         = p00;
            Ps[w16 + gid][c0 + 1]     = p01;
            Ps[w16 + gid + 8][c0]     = p10;
            Ps[w16 + gid + 8][c0 + 1] = p11;
            ts0 += __uint_as_float(p00) + __uint_as_float(p01);
            ts1 += __uint_as_float(p10) + __uint_as_float(p11);
        }
        ts0 += __shfl_xor_sync(0xffffffffu, ts0, 1);
        ts0 += __shfl_xor_sync(0xffffffffu, ts0, 2);
        ts1 += __shfl_xor_sync(0xffffffffu, ts1, 1);
        ts1 += __shfl_xor_sync(0xffffffffu, ts1, 2);
        l0 = l0 * al0 + ts0;
        l1 = l1 * al1 + ts1;

        #pragma unroll
        for (int nt = 0; nt < 8; nt++) {
            oacc[nt][0] *= al0; oacc[nt][1] *= al0;
            oacc[nt][2] *= al1; oacc[nt][3] *= al1;
        }
        __syncwarp();

        #pragma unroll
        for (int ks = 0; ks < 8; ks++) {
            uint32_t a0 = Ps[w16 + gid][ks * 8 + tig];
            uint32_t a1 = Ps[w16 + gid + 8][ks * 8 + tig];
            uint32_t a2 = Ps[w16 + gid][ks * 8 + tig + 4];
            uint32_t a3 = Ps[w16 + gid + 8][ks * 8 + tig + 4];
            #pragma unroll
            for (int nt = 0; nt < 8; nt++) {
                uint32_t b0 = Vs[ks * 8 + tig][nt * 8 + gid];
                uint32_t b1 = Vs[ks * 8 + tig + 4][nt * 8 + gid];
                mma_tf32(oacc[nt][0], oacc[nt][1], oacc[nt][2], oacc[nt][3],
                         a0, a1, a2, a3, b0, b1);
            }
        }
        __syncwarp();
    }

    float i0 = 1.f / l0, i1 = 1.f / l1;
    int r0 = q0 + w16 + gid;
    int r1 = r0 + 8;
    #pragma unroll
    for (int nt = 0; nt < 8; nt++) {
        int c0 = h * HD + nt * 8 + tig * 2;
        Aout[(size_t)r0 * D_MODEL + c0]     = oacc[nt][0] * i0;
        Aout[(size_t)r0 * D_MODEL + c0 + 1] = oacc[nt][1] * i0;
        Aout[(size_t)r1 * D_MODEL + c0]     = oacc[nt][2] * i1;
        Aout[(size_t)r1 * D_MODEL + c0 + 1] = oacc[nt][3] * i1;
    }
}

#define ATTN_SMEM (3 * ATK * ALD * 4)

extern "C" void kernel_launch(void* const* d_in, const int* in_sizes, int n_in,
                              void* d_out, int out_size) {
    const float* img      = (const float*)d_in[0];
    const float* temporal = (const float*)d_in[1];
    const float* txt      = (const float*)d_in[2];
    const float* vec      = (const float*)d_in[3];
    const float* pe       = (const float*)d_in[4];
    const float* mod_w    = (const float*)d_in[5];
    const float* mod_b    = (const float*)d_in[6];
    const float* qkv_w    = (const float*)d_in[7];
    const float* q_scale  = (const float*)d_in[8];
    const float* k_scale  = (const float*)d_in[9];
    const float* proj_w   = (const float*)d_in[10];
    const float* proj_b   = (const float*)d_in[11];
    const float* mlp_w1   = (const float*)d_in[12];
    const float* mlp_b1   = (const float*)d_in[13];
    const float* mlp_w2   = (const float*)d_in[14];
    const float* mlp_b2   = (const float*)d_in[15];
    float* out = (float*)d_out;

    static float *mod = 0, *xm = 0, *qkv = 0, *Qb = 0, *Kb = 0, *Vb = 0,
                 *attn = 0, *x1 = 0, *ym = 0, *hbuf = 0;
    if (!mod) {
        cudaGetSymbolAddress((void**)&mod,  g_mod);
        cudaGetSymbolAddress((void**)&xm,   g_xm);
        cudaGetSymbolAddress((void**)&qkv,  g_qkv);
        cudaGetSymbolAddress((void**)&Qb,   g_Q);
        cudaGetSymbolAddress((void**)&Kb,   g_K);
        cudaGetSymbolAddress((void**)&Vb,   g_V);
        cudaGetSymbolAddress((void**)&attn, g_attn);
        cudaGetSymbolAddress((void**)&x1,   g_x1);
        cudaGetSymbolAddress((void**)&ym,   g_ym);
        cudaGetSymbolAddress((void**)&hbuf, g_h);
        cudaFuncSetAttribute(attn_tc_kernel,
                             cudaFuncAttributeMaxDynamicSharedMemorySize, ATTN_SMEM);
        cudaFuncSetAttribute(gemm_tc_kernel,
                             cudaFuncAttributeMaxDynamicSharedMemorySize, GEMM_SMEM);
    }

    const int off_txt = 0;
    const int off_img = L_TXT;
    const int off_tmp = L_TXT + L_IMG;

    // 1. mod (silu fused)
    mod_kernel<<<(3 * 6144) / 256, 256>>>(vec, mod_w, mod_b, mod);

    // 2. LN1 + modulate
    lnmod_kernel<<<L_TXT, 256>>>(txt,      xm + (size_t)off_txt * D_MODEL, mod + 2 * 6144, mod + 2 * 6144 + 1024);
    lnmod_kernel<<<L_IMG, 256>>>(img,      xm + (size_t)off_img * D_MODEL, mod + 0,        mod + 1024);
    lnmod_kernel<<<L_TMP, 256>>>(temporal, xm + (size_t)off_tmp * D_MODEL, mod + 1 * 6144, mod + 1 * 6144 + 1024);

    // 3. QKV (batched z=3: txt->w2, img->w0, tmp->w1)
    {
        BArgs ba = {};
        int ao[3] = {off_txt, off_img, off_tmp};
        for (int z = 0; z < 3; z++) { ba.aoff[z] = ao[z]; ba.coff[z] = ao[z]; }
        ba.m[0] = 256; ba.m[1] = 1024; ba.m[2] = 1024;
        ba.woff[0] = 2LL * 1024 * 3072; ba.woff[1] = 0; ba.woff[2] = 1LL * 1024 * 3072;
        gemm_tc_kernel<<<dim3(3072 / TBN, 16, 3), 256, GEMM_SMEM>>>(xm, qkv_w, qkv, 3072, 1024,
                                                                    proj_b, mod, 0, ba);
    }

    // 4. RMS + scale + RoPE + scatter
    qkvpost_kernel<<<(L_ALL * NH) / 8, 256>>>(qkv, pe, q_scale, k_scale, Qb, Kb, Vb);

    // 5. attention
    attn_tc_kernel<<<dim3(L_ALL / ATQ, NH), 128, ATTN_SMEM>>>(Qb, Kb, Vb, attn);

    // 6. proj + gate + residual (batched z=3; residuals read original inputs directly)
    {
        BArgs ba = {};
        int ao[3] = {off_txt, off_img, off_tmp};
        int wi[3] = {2, 0, 1};
        const float* rp[3] = {txt, img, temporal};
        for (int z = 0; z < 3; z++) {
            ba.aoff[z] = ao[z]; ba.coff[z] = ao[z]; ba.roff[z] = 0;
            ba.resp[z] = rp[z];
            ba.woff[z] = (long long)wi[z] * 1024 * 1024;
            ba.boff[z] = wi[z] * 1024;
            ba.goff[z] = wi[z] * 6144 + 2048;
        }
        ba.m[0] = 256; ba.m[1] = 1024; ba.m[2] = 1024;
        gemm_tc_kernel<<<dim3(1024 / TBN, 16, 3), 256, GEMM_SMEM>>>(attn, proj_w, x1, 1024, 1024,
                                                                    proj_b, mod, 2, ba);
    }

    // 7. img + txt MLP (batched z=2); temporal must wait for final img
    lnmod_kernel<<<L_IMG, 256>>>(x1 + (size_t)off_img * D_MODEL, ym,
                                 mod + 0 * 6144 + 3072, mod + 0 * 6144 + 4096);
    lnmod_kernel<<<L_TXT, 256>>>(x1 + (size_t)off_txt * D_MODEL, ym + (size_t)1024 * D_MODEL,
                                 mod + 2 * 6144 + 3072, mod + 2 * 6144 + 4096);
    {
        BArgs ba = {};
        ba.aoff[0] = 0;    ba.coff[0] = 0;    ba.m[0] = 1024;
        ba.woff[0] = 0;    ba.boff[0] = 0;
        ba.aoff[1] = 1024; ba.coff[1] = 1024; ba.m[1] = 256;
        ba.woff[1] = 2LL * 1024 * 4096; ba.boff[1] = 2 * 4096;
        gemm_tc_kernel<<<dim3(4096 / TBN, 16, 2), 256, GEMM_SMEM>>>(ym, mlp_w1, hbuf, 4096, 1024,
                                                                    mlp_b1, mod, 1, ba);
    }
    {
        BArgs ba = {};
        // z0: img -> out rows [0,1024), res = x1 img rows
        ba.aoff[0] = 0;    ba.coff[0] = 0;    ba.roff[0] = off_img; ba.resp[0] = x1; ba.m[0] = 1024;
        ba.woff[0] = 0;    ba.boff[0] = 0;    ba.goff[0] = 0 * 6144 + 5120;
        // z1: txt -> out rows [2048,2304), res = x1 txt rows
        ba.aoff[1] = 1024; ba.coff[1] = 2048; ba.roff[1] = off_txt; ba.resp[1] = x1; ba.m[1] = 256;
        ba.woff[1] = 2LL * 4096 * 1024; ba.boff[1] = 2 * 1024; ba.goff[1] = 2 * 6144 + 5120;
        gemm_tc_kernel<<<dim3(1024 / TBN, 16, 2), 256, GEMM_SMEM>>>(hbuf, mlp_w2, out, 1024, 4096,
                                                                    mlp_b2, mod, 2, ba);
    }

    // 8. temporal MLP: LN of FINAL img (reference quirk), residual = x1 tmp rows
    lnmod_kernel<<<L_TMP, 256>>>(out, ym, mod + 1 * 6144 + 3072, mod + 1 * 6144 + 4096);
    {
        BArgs ba = {};
        ba.aoff[0] = 0; ba.coff[0] = 0; ba.m[0] = 1024;
        ba.woff[0] = 1LL * 1024 * 4096; ba.boff[0] = 4096;
        gemm_tc_kernel<<<dim3(4096 / TBN, 16, 1), 256, GEMM_SMEM>>>(ym, mlp_w1, hbuf, 4096, 1024,
                                                                    mlp_b1, mod, 1, ba);
    }
    {
        BArgs ba = {};
        ba.aoff[0] = 0; ba.coff[0] = 1024; ba.roff[0] = off_tmp; ba.resp[0] = x1; ba.m[0] = 1024;
        ba.woff[0] = 1LL * 4096 * 1024; ba.boff[0] = 1024; ba.goff[0] = 1 * 6144 + 5120;
        gemm_tc_kernel<<<dim3(1024 / TBN, 16, 1), 256, GEMM_SMEM>>>(hbuf, mlp_w2, out, 1024, 4096,
                                                                    mlp_b2, mod, 2, ba);
    }
}

// round 13
// speedup vs baseline: 1.0645x; 1.0036x over previous
#include <cuda_runtime.h>
#include <cuda_bf16.h>
#include <math.h>
#include <stdint.h>

// ---------------- problem constants ----------------
#define L_TXT 256
#define L_IMG 1024
#define L_TMP 1024
#define L_ALL 2304          // txt + img + tmp
#define D_MODEL 1024
#define NH 16
#define HD 64
#define D_MLP 4096
#define EPS 1e-6f
#define ATTN_SCALE 0.125f   // 1/sqrt(64)

// ---------------- scratch (static device memory; no allocation) ----------------
__device__ float g_mod[3 * 6144];
__device__ float g_xm[L_ALL * D_MODEL];        // LN1-modulated, concat order [txt|img|tmp]
__device__ float g_qkv[L_ALL * 3 * D_MODEL];   // QKV gemm out, same row order
__device__ float g_Q[NH * L_ALL * HD];         // tf32-rounded, pre-scaled by ATTN_SCALE
__device__ float g_K[NH * L_ALL * HD];         // tf32-rounded
__device__ float g_V[NH * L_ALL * HD];         // tf32-rounded
__device__ float g_attn[L_ALL * D_MODEL];      // [l][h*64+d], concat order
__device__ float g_x1[L_ALL * D_MODEL];        // post-proj residual, concat order
__device__ float g_ym[1280 * D_MODEL];         // LN2-modulated (img rows 0..1023, txt rows 1024..1279)
__device__ float g_h[1280 * D_MLP];            // MLP hidden

// ---------------- helpers ----------------
__device__ __forceinline__ float gelu_tanh(float x) {
    const float c = 0.7978845608028654f; // sqrt(2/pi)
    float x3 = x * x * x;
    return 0.5f * x * (1.f + tanhf(c * (x + 0.044715f * x3)));
}

__device__ __forceinline__ uint32_t f2tf32(float f) {
    uint32_t u;
    asm("cvt.rna.tf32.f32 %0, %1;" : "=r"(u) : "f"(f));
    return u;
}

__device__ __forceinline__ void mma_tf32(float& d0, float& d1, float& d2, float& d3,
                                         uint32_t a0, uint32_t a1, uint32_t a2, uint32_t a3,
                                         uint32_t b0, uint32_t b1) {
    asm volatile(
        "mma.sync.aligned.m16n8k8.row.col.f32.tf32.tf32.f32 "
        "{%0,%1,%2,%3}, {%4,%5,%6,%7}, {%8,%9}, {%0,%1,%2,%3};"
        : "+f"(d0), "+f"(d1), "+f"(d2), "+f"(d3)
        : "r"(a0), "r"(a1), "r"(a2), "r"(a3), "r"(b0), "r"(b1));
}

// ---------------- mod = silu(vec) @ mod_w + mod_b  (3 x 6144 outputs; silu fused) ----------------
__global__ void mod_kernel(const float* __restrict__ vecp, const float* __restrict__ mod_w,
                           const float* __restrict__ mod_b, float* __restrict__ mod) {
    __shared__ float s_sv[D_MODEL];
    for (int i = threadIdx.x; i < D_MODEL; i += 256) {
        float x = vecp[i];
        s_sv[i] = x / (1.f + expf(-x));
    }
    __syncthreads();
    int o = blockIdx.x * 256 + threadIdx.x;       // 0 .. 3*6144-1
    int i = o / 6144;
    int j = o - i * 6144;
    const float* w = mod_w + (size_t)i * D_MODEL * 6144 + j;
    float acc = 0.f;
    #pragma unroll 8
    for (int d = 0; d < D_MODEL; ++d) acc = fmaf(s_sv[d], w[(size_t)d * 6144], acc);
    mod[o] = acc + mod_b[o];
}

// ---------------- LN + modulate: out = (1+sc)*ln(x) + sh ----------------
__global__ void lnmod_kernel(const float* __restrict__ x, float* __restrict__ out,
                             const float* __restrict__ sh, const float* __restrict__ sc) {
    int r = blockIdx.x;
    const float* xr = x + (size_t)r * D_MODEL;
    int t = threadIdx.x; // 256
    float v[4]; float sum = 0.f, sq = 0.f;
    #pragma unroll
    for (int i = 0; i < 4; i++) { float f = xr[t + i * 256]; v[i] = f; sum += f; sq += f * f; }
    #pragma unroll
    for (int o = 16; o; o >>= 1) {
        sum += __shfl_xor_sync(0xffffffffu, sum, o);
        sq  += __shfl_xor_sync(0xffffffffu, sq, o);
    }
    __shared__ float ssum[8], ssq[8];
    int w = t >> 5, lane = t & 31;
    if (lane == 0) { ssum[w] = sum; ssq[w] = sq; }
    __syncthreads();
    if (t == 0) {
        float S = 0.f, Q = 0.f;
        #pragma unroll
        for (int i = 0; i < 8; i++) { S += ssum[i]; Q += ssq[i]; }
        float mean = S * (1.f / D_MODEL);
        float var  = Q * (1.f / D_MODEL) - mean * mean;
        ssum[0] = mean; ssq[0] = rsqrtf(var + EPS);
    }
    __syncthreads();
    float mean = ssum[0], inv = ssq[0];
    float* orow = out + (size_t)r * D_MODEL;
    #pragma unroll
    for (int i = 0; i < 4; i++) {
        int d = t + i * 256;
        orow[d] = (1.f + sc[d]) * ((v[i] - mean) * inv) + sh[d];
    }
}

// ---------------- tf32 tensor-core GEMM, 64x128x32 tiles, fragment-packed, z-batched ----------------
// epi 0: C = acc;  epi 1: C = gelu(acc + bias);  epi 2: C = resp[z] + gate*(acc + bias)
#define TBM 64
#define TBN 128
#define TBK 32
#define A_OCT 516           // 4*32*4 + 4
#define A_STAGE (4 * A_OCT)
#define B_NB 66
#define B_OCT 1058          // 16*66 + 2
#define B_STAGE (4 * B_OCT)
#define GEMM_SMEM ((2 * A_STAGE + 2 * B_STAGE) * 4)   // 50368 bytes

struct BArgs {
    const float* resp[3]; // residual base pointer per z (epi 2)
    int aoff[3];      // A row offset per z
    int coff[3];      // C row offset per z
    int roff[3];      // res row offset per z (applied to resp[z])
    int m[3];         // rows per z
    long long woff[3];// weight element offset per z
    int boff[3];      // bias element offset per z
    int goff[3];      // gate element offset per z
};

__global__ void __launch_bounds__(256) gemm_tc_kernel(
        const float* __restrict__ A, const float* __restrict__ W,
        float* __restrict__ C, int N, int K,
        const float* __restrict__ bias,
        const float* __restrict__ gate,
        int epi, BArgs ba) {
    int z = blockIdx.z;
    int brow = blockIdx.y, bcol = blockIdx.x;
    if (brow * TBM >= ba.m[z]) return;

    extern __shared__ uint32_t gsm[];
    uint32_t (*As)[A_STAGE] = (uint32_t(*)[A_STAGE])gsm;
    uint32_t (*Bs)[B_STAGE] = (uint32_t(*)[B_STAGE])(gsm + 2 * A_STAGE);

    int tid  = threadIdx.x;
    int warp = tid >> 5;
    int lane = tid & 31;
    int gid  = lane >> 2;
    int tig  = lane & 3;
    int wm2  = (warp >> 2) * 2;     // mblk base (0 or 2)
    int wn8  = (warp & 3) * 4;      // nblk base

    const float* Ab = A + (size_t)ba.aoff[z] * K;
    const float* Bb = W + ba.woff[z];

    int al0 = tid, al1 = tid + 256;
    int a_row0 = al0 >> 3, a_kq0 = (al0 & 7) * 4;
    int a_row1 = al1 >> 3, a_kq1 = (al1 & 7) * 4;
    int abase0 = (a_kq0 >> 3) * A_OCT + (a_row0 >> 4) * 128 + (a_row0 & 7) * 16
               + ((a_row0 >> 3) & 1) * 2 + ((a_kq0 >> 2) & 1);
    int abase1 = (a_kq1 >> 3) * A_OCT + (a_row1 >> 4) * 128 + (a_row1 & 7) * 16
               + ((a_row1 >> 3) & 1) * 2 + ((a_kq1 >> 2) & 1);

    int b_row = tid >> 6;              // 0..3
    int b_col = (tid & 63) * 2;        // 0..126

    const float* Aptr0 = Ab + (size_t)(brow * TBM + a_row0) * K + a_kq0;
    const float* Aptr1 = Ab + (size_t)(brow * TBM + a_row1) * K + a_kq1;
    const float* Bptr  = Bb + (size_t)b_row * N + bcol * TBN + b_col;

    float acc[2][4][4];
    #pragma unroll
    for (int i = 0; i < 2; i++)
        #pragma unroll
        for (int j = 0; j < 4; j++)
            #pragma unroll
            for (int c = 0; c < 4; c++) acc[i][j][c] = 0.f;

    int iters = K / TBK;

    float4 av0 = *(const float4*)(Aptr0);
    float4 av1 = *(const float4*)(Aptr1);
    float2 bv[8];
    #pragma unroll
    for (int r = 0; r < 8; r++)
        bv[r] = *(const float2*)(Bptr + (size_t)(r * 4) * N);

    #define STORE_TILE(BUF) do {                                                     \
        As[BUF][abase0 + 0]  = __float_as_uint(av0.x);                               \
        As[BUF][abase0 + 4]  = __float_as_uint(av0.y);                               \
        As[BUF][abase0 + 8]  = __float_as_uint(av0.z);                               \
        As[BUF][abase0 + 12] = __float_as_uint(av0.w);                               \
        As[BUF][abase1 + 0]  = __float_as_uint(av1.x);                               \
        As[BUF][abase1 + 4]  = __float_as_uint(av1.y);                               \
        As[BUF][abase1 + 8]  = __float_as_uint(av1.z);                               \
        As[BUF][abase1 + 12] = __float_as_uint(av1.w);                               \
        _Pragma("unroll")                                                            \
        for (int r = 0; r < 8; r++) {                                                \
            int k   = b_row + r * 4;                                                 \
            int oct = k >> 3;                                                        \
            int j   = k & 7;                                                         \
            int jm  = j & 3;                                                         \
            int sl  = j >> 2;                                                        \
            int n7  = b_col & 7;                                                     \
            int nbl = b_col >> 3;                                                    \
            uint32_t* bb = &Bs[BUF][oct * B_OCT + nbl * B_NB + sl];                  \
            bb[(n7 * 4 + jm) * 2]       = __float_as_uint(bv[r].x);                  \
            bb[((n7 + 1) * 4 + jm) * 2] = __float_as_uint(bv[r].y);                  \
        }                                                                            \
    } while (0)

    STORE_TILE(0);
    __syncthreads();

    for (int it = 0; it < iters; ++it) {
        int cur = it & 1;
        if (it + 1 < iters) {
            int k0 = (it + 1) * TBK;
            av0 = *(const float4*)(Aptr0 + k0);
            av1 = *(const float4*)(Aptr1 + k0);
            #pragma unroll
            for (int r = 0; r < 8; r++)
                bv[r] = *(const float2*)(Bptr + (size_t)(k0 + r * 4) * N);
        }

        #pragma unroll
        for (int oct = 0; oct < 4; oct++) {
            uint4 ua[2];
            #pragma unroll
            for (int mt = 0; mt < 2; mt++)
                ua[mt] = *(const uint4*)&As[cur][oct * A_OCT + (wm2 + mt) * 128 + lane * 4];
            uint2 ub[4];
            #pragma unroll
            for (int nt = 0; nt < 4; nt++)
                ub[nt] = *(const uint2*)&Bs[cur][oct * B_OCT + (wn8 + nt) * B_NB + lane * 2];
            #pragma unroll
            for (int mt = 0; mt < 2; mt++)
                #pragma unroll
                for (int nt = 0; nt < 4; nt++)
                    mma_tf32(acc[mt][nt][0], acc[mt][nt][1], acc[mt][nt][2], acc[mt][nt][3],
                             ua[mt].x, ua[mt].z, ua[mt].y, ua[mt].w,
                             ub[nt].x, ub[nt].y);
        }

        if (it + 1 < iters) {
            int nxt = cur ^ 1;
            STORE_TILE(nxt);
            __syncthreads();
        }
    }
    #undef STORE_TILE

    // epilogue
    int wm = (warp >> 2) * 32;
    int wn = (warp & 3) * 32;
    int crow = ba.coff[z];
    int rrow = ba.roff[z];
    const float* resz = ba.resp[z];
    int bo = ba.boff[z], go = ba.goff[z];
    #pragma unroll
    for (int mt = 0; mt < 2; mt++) {
        int lrow0 = brow * TBM + wm + mt * 16 + gid;
        int lrow1 = lrow0 + 8;
        #pragma unroll
        for (int nt = 0; nt < 4; nt++) {
            int col0 = bcol * TBN + wn + nt * 8 + tig * 2;
            int col1 = col0 + 1;
            float v0 = acc[mt][nt][0], v1 = acc[mt][nt][1];
            float v2 = acc[mt][nt][2], v3 = acc[mt][nt][3];
            if (epi == 1) {
                v0 = gelu_tanh(v0 + bias[bo + col0]); v1 = gelu_tanh(v1 + bias[bo + col1]);
                v2 = gelu_tanh(v2 + bias[bo + col0]); v3 = gelu_tanh(v3 + bias[bo + col1]);
            } else if (epi == 2) {
                v0 = resz[(size_t)(rrow + lrow0) * N + col0] + gate[go + col0] * (v0 + bias[bo + col0]);
                v1 = resz[(size_t)(rrow + lrow0) * N + col1] + gate[go + col1] * (v1 + bias[bo + col1]);
                v2 = resz[(size_t)(rrow + lrow1) * N + col0] + gate[go + col0] * (v2 + bias[bo + col0]);
                v3 = resz[(size_t)(rrow + lrow1) * N + col1] + gate[go + col1] * (v3 + bias[bo + col1]);
            }
            C[(size_t)(crow + lrow0) * N + col0] = v0;
            C[(size_t)(crow + lrow0) * N + col1] = v1;
            C[(size_t)(crow + lrow1) * N + col0] = v2;
            C[(size_t)(crow + lrow1) * N + col1] = v3;
        }
    }
}

// ---------------- QKV post: RMS + scale + RoPE + tf32 pre-round + scatter ----------------
// Q is pre-scaled by ATTN_SCALE (power of 2; commutes exactly with tf32 rounding).
__global__ void qkvpost_kernel(const float* __restrict__ Y, const float* __restrict__ pe,
                               const float* __restrict__ q_scale, const float* __restrict__ k_scale,
                               float* __restrict__ Q, float* __restrict__ K, float* __restrict__ V) {
    int gw = blockIdx.x * 8 + (threadIdx.x >> 5);   // warp id: 0 .. 2304*16-1
    int lane = threadIdx.x & 31;
    int l = gw >> 4;
    int h = gw & 15;
    int i = (l < L_TXT) ? 2 : (l < (L_TXT + L_IMG) ? 0 : 1);
    bool is_tmp = (l >= L_TXT + L_IMG);

    const float* row = Y + (size_t)l * 3072 + h * HD;
    float q0 = row[2 * lane],        q1 = row[2 * lane + 1];
    float k0 = row[1024 + 2 * lane], k1 = row[1024 + 2 * lane + 1];
    float v0 = row[2048 + 2 * lane], v1 = row[2048 + 2 * lane + 1];

    float qs = q0 * q0 + q1 * q1;
    float ks = k0 * k0 + k1 * k1;
    #pragma unroll
    for (int o = 16; o; o >>= 1) {
        qs += __shfl_xor_sync(0xffffffffu, qs, o);
        ks += __shfl_xor_sync(0xffffffffu, ks, o);
    }
    float qinv = rsqrtf(qs * (1.f / HD) + EPS);
    float kinv = rsqrtf(ks * (1.f / HD) + EPS);

    float qn0 = q0 * qinv * q_scale[i * HD + 2 * lane];
    float qn1 = q1 * qinv * q_scale[i * HD + 2 * lane + 1];
    float kn0 = k0 * kinv * k_scale[i * HD + 2 * lane];
    float kn1 = k1 * kinv * k_scale[i * HD + 2 * lane + 1];

    const float* p = pe + ((size_t)l * 32 + lane) * 4;
    float p00 = p[0], p01 = p[1], p10 = p[2], p11 = p[3];

    size_t base = ((size_t)h * L_ALL + l) * HD + 2 * lane;
    Q[base]     = __uint_as_float(f2tf32((p00 * qn0 + p01 * qn1) * ATTN_SCALE));
    Q[base + 1] = __uint_as_float(f2tf32((p10 * qn0 + p11 * qn1) * ATTN_SCALE));
    K[base]     = __uint_as_float(f2tf32(p00 * kn0 + p01 * kn1));
    K[base + 1] = __uint_as_float(f2tf32(p10 * kn0 + p11 * kn1));
    if (is_tmp) {
        // reference quirk: v for temporal rows = RMS'd+scaled q BEFORE RoPE.
        // Pre-round to tf32: PV mma would truncate anyway -> identical math.
        V[base]     = __uint_as_float(f2tf32(qn0));
        V[base + 1] = __uint_as_float(f2tf32(qn1));
    } else {
        V[base]     = __uint_as_float(f2tf32(v0));
        V[base + 1] = __uint_as_float(f2tf32(v1));
    }
}

// ---------------- flash attention on tensor cores (tf32 mma, inputs pre-rounded) ----------------
#define ATQ 64
#define ATK 64
#define ALD 68

__global__ void __launch_bounds__(128) attn_tc_kernel(
        const float* __restrict__ Q, const float* __restrict__ K,
        const float* __restrict__ V, float* __restrict__ Aout) {
    extern __shared__ uint32_t dyn[];
    uint32_t (*Ks)[ALD] = (uint32_t(*)[ALD])dyn;
    uint32_t (*Vs)[ALD] = (uint32_t(*)[ALD])(dyn + ATK * ALD);
    uint32_t (*Ps)[ALD] = (uint32_t(*)[ALD])(dyn + 2 * ATK * ALD);

    int h   = blockIdx.y;
    int q0  = blockIdx.x * ATQ;
    int tid = threadIdx.x;          // 128
    int warp = tid >> 5;
    int lane = tid & 31;
    int gid  = lane >> 2;
    int tig  = lane & 3;
    int w16  = warp * 16;

    const uint32_t* Qh = (const uint32_t*)(Q + (size_t)h * L_ALL * HD);
    const uint32_t* Kh = (const uint32_t*)(K + (size_t)h * L_ALL * HD);
    const uint32_t* Vh = (const uint32_t*)(V + (size_t)h * L_ALL * HD);

    // stage Q (already tf32-rounded + pre-scaled): raw uint4 copies
    #pragma unroll
    for (int i = 0; i < 8; i++) {
        int linear = tid + i * 128;
        int r = linear >> 4;
        int c4 = (linear & 15) * 4;
        uint4 qv = *(const uint4*)(Qh + (size_t)(q0 + r) * HD + c4);
        *(uint4*)&Ps[r][c4] = qv;
    }
    __syncthreads();

    uint32_t qf[8][4];
    #pragma unroll
    for (int ks = 0; ks < 8; ks++) {
        qf[ks][0] = Ps[w16 + gid][ks * 8 + tig];
        qf[ks][1] = Ps[w16 + gid + 8][ks * 8 + tig];
        qf[ks][2] = Ps[w16 + gid][ks * 8 + tig + 4];
        qf[ks][3] = Ps[w16 + gid + 8][ks * 8 + tig + 4];
    }

    float oacc[8][4];
    #pragma unroll
    for (int nt = 0; nt < 8; nt++)
        #pragma unroll
        for (int c = 0; c < 4; c++) oacc[nt][c] = 0.f;
    float m0 = -INFINITY, m1 = -INFINITY, l0 = 0.f, l1 = 0.f;

    for (int kb = 0; kb < L_ALL; kb += ATK) {
        __syncthreads();
        #pragma unroll
        for (int i = 0; i < 8; i++) {
            int linear = tid + i * 128;
            int r = linear >> 4;
            int c4 = (linear & 15) * 4;
            uint4 kv = *(const uint4*)(Kh + (size_t)(kb + r) * HD + c4);
            uint4 vv = *(const uint4*)(Vh + (size_t)(kb + r) * HD + c4);
            *(uint4*)&Ks[r][c4] = kv;
            *(uint4*)&Vs[r][c4] = vv;
        }
        __syncthreads();

        float sacc[8][4];
        #pragma unroll
        for (int nt = 0; nt < 8; nt++)
            #pragma unroll
            for (int c = 0; c < 4; c++) sacc[nt][c] = 0.f;
        #pragma unroll
        for (int ks = 0; ks < 8; ks++) {
            #pragma unroll
            for (int nt = 0; nt < 8; nt++) {
                uint32_t b0 = Ks[nt * 8 + gid][ks * 8 + tig];
                uint32_t b1 = Ks[nt * 8 + gid][ks * 8 + tig + 4];
                mma_tf32(sacc[nt][0], sacc[nt][1], sacc[nt][2], sacc[nt][3],
                         qf[ks][0], qf[ks][1], qf[ks][2], qf[ks][3], b0, b1);
            }
        }

        float t0 = -INFINITY, t1 = -INFINITY;
        #pragma unroll
        for (int nt = 0; nt < 8; nt++) {
            t0 = fmaxf(t0, fmaxf(sacc[nt][0], sacc[nt][1]));
            t1 = fmaxf(t1, fmaxf(sacc[nt][2], sacc[nt][3]));
        }
        t0 = fmaxf(t0, __shfl_xor_sync(0xffffffffu, t0, 1));
        t0 = fmaxf(t0, __shfl_xor_sync(0xffffffffu, t0, 2));
        t1 = fmaxf(t1, __shfl_xor_sync(0xffffffffu, t1, 1));
        t1 = fmaxf(t1, __shfl_xor_sync(0xffffffffu, t1, 2));
        float mn0 = fmaxf(m0, t0), mn1 = fmaxf(m1, t1);
        float al0 = __expf(m0 - mn0), al1 = __expf(m1 - mn1);
        m0 = mn0; m1 = mn1;

        float ts0 = 0.f, ts1 = 0.f;
        #pragma unroll
        for (int nt = 0; nt < 8; nt++) {
            int c0 = nt * 8 + tig * 2;
            uint32_t p00 = f2tf32(__expf(sacc[nt][0] - mn0));
            uint32_t p01 = f2tf32(__expf(sacc[nt][1] - mn0));
            uint32_t p10 = f2tf32(__expf(sacc[nt][2] - mn1));
            uint32_t p11 = f2tf32(__expf(sacc[nt][3] - mn1));
            Ps[w16 + gid][c0]         = p00;
            Ps[w16 + gid][c0 + 1]     = p01;
            Ps[w16 + gid + 8][c0]     = p10;
            Ps[w16 + gid + 8][c0 + 1] = p11;
            ts0 += __uint_as_float(p00) + __uint_as_float(p01);
            ts1 += __uint_as_float(p10) + __uint_as_float(p11);
        }
        ts0 += __shfl_xor_sync(0xffffffffu, ts0, 1);
        ts0 += __shfl_xor_sync(0xffffffffu, ts0, 2);
        ts1 += __shfl_xor_sync(0xffffffffu, ts1, 1);
        ts1 += __shfl_xor_sync(0xffffffffu, ts1, 2);
        l0 = l0 * al0 + ts0;
        l1 = l1 * al1 + ts1;

        #pragma unroll
        for (int nt = 0; nt < 8; nt++) {
            oacc[nt][0] *= al0; oacc[nt][1] *= al0;
            oacc[nt][2] *= al1; oacc[nt][3] *= al1;
        }
        __syncwarp();

        #pragma unroll
        for (int ks = 0; ks < 8; ks++) {
            uint32_t a0 = Ps[w16 + gid][ks * 8 + tig];
            uint32_t a1 = Ps[w16 + gid + 8][ks * 8 + tig];
            uint32_t a2 = Ps[w16 + gid][ks * 8 + tig + 4];
            uint32_t a3 = Ps[w16 + gid + 8][ks * 8 + tig + 4];
            #pragma unroll
            for (int nt = 0; nt < 8; nt++) {
                uint32_t b0 = Vs[ks * 8 + tig][nt * 8 + gid];
                uint32_t b1 = Vs[ks * 8 + tig + 4][nt * 8 + gid];
                mma_tf32(oacc[nt][0], oacc[nt][1], oacc[nt][2], oacc[nt][3],
                         a0, a1, a2, a3, b0, b1);
            }
        }
        __syncwarp();
    }

    float i0 = 1.f / l0, i1 = 1.f / l1;
    int r0 = q0 + w16 + gid;
    int r1 = r0 + 8;
    #pragma unroll
    for (int nt = 0; nt < 8; nt++) {
        int c0 = h * HD + nt * 8 + tig * 2;
        Aout[(size_t)r0 * D_MODEL + c0]     = oacc[nt][0] * i0;
        Aout[(size_t)r0 * D_MODEL + c0 + 1] = oacc[nt][1] * i0;
        Aout[(size_t)r1 * D_MODEL + c0]     = oacc[nt][2] * i1;
        Aout[(size_t)r1 * D_MODEL + c0 + 1] = oacc[nt][3] * i1;
    }
}

#define ATTN_SMEM (3 * ATK * ALD * 4)

extern "C" void kernel_launch(void* const* d_in, const int* in_sizes, int n_in,
                              void* d_out, int out_size) {
    const float* img      = (const float*)d_in[0];
    const float* temporal = (const float*)d_in[1];
    const float* txt      = (const float*)d_in[2];
    const float* vec      = (const float*)d_in[3];
    const float* pe       = (const float*)d_in[4];
    const float* mod_w    = (const float*)d_in[5];
    const float* mod_b    = (const float*)d_in[6];
    const float* qkv_w    = (const float*)d_in[7];
    const float* q_scale  = (const float*)d_in[8];
    const float* k_scale  = (const float*)d_in[9];
    const float* proj_w   = (const float*)d_in[10];
    const float* proj_b   = (const float*)d_in[11];
    const float* mlp_w1   = (const float*)d_in[12];
    const float* mlp_b1   = (const float*)d_in[13];
    const float* mlp_w2   = (const float*)d_in[14];
    const float* mlp_b2   = (const float*)d_in[15];
    float* out = (float*)d_out;

    static float *mod = 0, *xm = 0, *qkv = 0, *Qb = 0, *Kb = 0, *Vb = 0,
                 *attn = 0, *x1 = 0, *ym = 0, *hbuf = 0;
    if (!mod) {
        cudaGetSymbolAddress((void**)&mod,  g_mod);
        cudaGetSymbolAddress((void**)&xm,   g_xm);
        cudaGetSymbolAddress((void**)&qkv,  g_qkv);
        cudaGetSymbolAddress((void**)&Qb,   g_Q);
        cudaGetSymbolAddress((void**)&Kb,   g_K);
        cudaGetSymbolAddress((void**)&Vb,   g_V);
        cudaGetSymbolAddress((void**)&attn, g_attn);
        cudaGetSymbolAddress((void**)&x1,   g_x1);
        cudaGetSymbolAddress((void**)&ym,   g_ym);
        cudaGetSymbolAddress((void**)&hbuf, g_h);
        cudaFuncSetAttribute(attn_tc_kernel,
                             cudaFuncAttributeMaxDynamicSharedMemorySize, ATTN_SMEM);
        cudaFuncSetAttribute(gemm_tc_kernel,
                             cudaFuncAttributeMaxDynamicSharedMemorySize, GEMM_SMEM);
    }

    const int off_txt = 0;
    const int off_img = L_TXT;
    const int off_tmp = L_TXT + L_IMG;

    // 1. mod (silu fused)
    mod_kernel<<<(3 * 6144) / 256, 256>>>(vec, mod_w, mod_b, mod);

    // 2. LN1 + modulate
    lnmod_kernel<<<L_TXT, 256>>>(txt,      xm + (size_t)off_txt * D_MODEL, mod + 2 * 6144, mod + 2 * 6144 + 1024);
    lnmod_kernel<<<L_IMG, 256>>>(img,      xm + (size_t)off_img * D_MODEL, mod + 0,        mod + 1024);
    lnmod_kernel<<<L_TMP, 256>>>(temporal, xm + (size_t)off_tmp * D_MODEL, mod + 1 * 6144, mod + 1 * 6144 + 1024);

    // 3. QKV (batched z=3: txt->w2, img->w0, tmp->w1)
    {
        BArgs ba = {};
        int ao[3] = {off_txt, off_img, off_tmp};
        for (int z = 0; z < 3; z++) { ba.aoff[z] = ao[z]; ba.coff[z] = ao[z]; }
        ba.m[0] = 256; ba.m[1] = 1024; ba.m[2] = 1024;
        ba.woff[0] = 2LL * 1024 * 3072; ba.woff[1] = 0; ba.woff[2] = 1LL * 1024 * 3072;
        gemm_tc_kernel<<<dim3(3072 / TBN, 16, 3), 256, GEMM_SMEM>>>(xm, qkv_w, qkv, 3072, 1024,
                                                                    proj_b, mod, 0, ba);
    }

    // 4. RMS + scale + RoPE + tf32 pre-round + scatter
    qkvpost_kernel<<<(L_ALL * NH) / 8, 256>>>(qkv, pe, q_scale, k_scale, Qb, Kb, Vb);

    // 5. attention
    attn_tc_kernel<<<dim3(L_ALL / ATQ, NH), 128, ATTN_SMEM>>>(Qb, Kb, Vb, attn);

    // 6. proj + gate + residual (batched z=3; residuals read original inputs directly)
    {
        BArgs ba = {};
        int ao[3] = {off_txt, off_img, off_tmp};
        int wi[3] = {2, 0, 1};
        const float* rp[3] = {txt, img, temporal};
        for (int z = 0; z < 3; z++) {
            ba.aoff[z] = ao[z]; ba.coff[z] = ao[z]; ba.roff[z] = 0;
            ba.resp[z] = rp[z];
            ba.woff[z] = (long long)wi[z] * 1024 * 1024;
            ba.boff[z] = wi[z] * 1024;
            ba.goff[z] = wi[z] * 6144 + 2048;
        }
        ba.m[0] = 256; ba.m[1] = 1024; ba.m[2] = 1024;
        gemm_tc_kernel<<<dim3(1024 / TBN, 16, 3), 256, GEMM_SMEM>>>(attn, proj_w, x1, 1024, 1024,
                                                                    proj_b, mod, 2, ba);
    }

    // 7. img + txt MLP (batched z=2); temporal must wait for final img
    lnmod_kernel<<<L_IMG, 256>>>(x1 + (size_t)off_img * D_MODEL, ym,
                                 mod + 0 * 6144 + 3072, mod + 0 * 6144 + 4096);
    lnmod_kernel<<<L_TXT, 256>>>(x1 + (size_t)off_txt * D_MODEL, ym + (size_t)1024 * D_MODEL,
                                 mod + 2 * 6144 + 3072, mod + 2 * 6144 + 4096);
    {
        BArgs ba = {};
        ba.aoff[0] = 0;    ba.coff[0] = 0;    ba.m[0] = 1024;
        ba.woff[0] = 0;    ba.boff[0] = 0;
        ba.aoff[1] = 1024; ba.coff[1] = 1024; ba.m[1] = 256;
        ba.woff[1] = 2LL * 1024 * 4096; ba.boff[1] = 2 * 4096;
        gemm_tc_kernel<<<dim3(4096 / TBN, 16, 2), 256, GEMM_SMEM>>>(ym, mlp_w1, hbuf, 4096, 1024,
                                                                    mlp_b1, mod, 1, ba);
    }
    {
        BArgs ba = {};
        ba.aoff[0] = 0;    ba.coff[0] = 0;    ba.roff[0] = off_img; ba.resp[0] = x1; ba.m[0] = 1024;
        ba.woff[0] = 0;    ba.boff[0] = 0;    ba.goff[0] = 0 * 6144 + 5120;
        ba.aoff[1] = 1024; ba.coff[1] = 2048; ba.roff[1] = off_txt; ba.resp[1] = x1; ba.m[1] = 256;
        ba.woff[1] = 2LL * 4096 * 1024; ba.boff[1] = 2 * 1024; ba.goff[1] = 2 * 6144 + 5120;
        gemm_tc_kernel<<<dim3(1024 / TBN, 16, 2), 256, GEMM_SMEM>>>(hbuf, mlp_w2, out, 1024, 4096,
                                                                    mlp_b2, mod, 2, ba);
    }

    // 8. temporal MLP: LN of FINAL img (reference quirk), residual = x1 tmp rows
    lnmod_kernel<<<L_TMP, 256>>>(out, ym, mod + 1 * 6144 + 3072, mod + 1 * 6144 + 4096);
    {
        BArgs ba = {};
        ba.aoff[0] = 0; ba.coff[0] = 0; ba.m[0] = 1024;
        ba.woff[0] = 1LL * 1024 * 4096; ba.boff[0] = 4096;
        gemm_tc_kernel<<<dim3(4096 / TBN, 16, 1), 256, GEMM_SMEM>>>(ym, mlp_w1, hbuf, 4096, 1024,
                                                                    mlp_b1, mod, 1, ba);
    }
    {
        BArgs ba = {};
        ba.aoff[0] = 0; ba.coff[0] = 1024; ba.roff[0] = off_tmp; ba.resp[0] = x1; ba.m[0] = 1024;
        ba.woff[0] = 1LL * 4096 * 1024; ba.boff[0] = 1024; ba.goff[0] = 1 * 6144 + 5120;
        gemm_tc_kernel<<<dim3(1024 / TBN, 16, 1), 256, GEMM_SMEM>>>(hbuf, mlp_w2, out, 1024, 4096,
                                                                    mlp_b2, mod, 2, ba);
    }
}